// round 14
// baseline (speedup 1.0000x reference)
#include <cuda_runtime.h>

#define BATCH 4
#define NPTS  16384
#define KNN   16
#define CIN   32
#define D2    32
#define DD    64
#define DOUT  128
#define P_TOT (BATCH*NPTS)
#define ST    20
#define WPB   6     // warps per block for kB/kC1 (192-thread blocks)

typedef unsigned long long u64;

__device__ __forceinline__ u64 fma2(u64 a, u64 b, u64 c){
    u64 d; asm("fma.rn.f32x2 %0, %1, %2, %3;" : "=l"(d) : "l"(a), "l"(b), "l"(c)); return d;
}
__device__ __forceinline__ float2 unpk(u64 v){
    float2 f; asm("mov.b64 {%0, %1}, %2;" : "=f"(f.x), "=f"(f.y) : "l"(v)); return f;
}
__device__ __forceinline__ u64 pck(float x, float y){
    u64 v; asm("mov.b64 %0, {%1, %2};" : "=l"(v) : "f"(x), "f"(y)); return v;
}

// ---- scratch ----
__device__ float g_fpc  [P_TOT*CIN];
__device__ float g_featT[P_TOT*CIN];
__device__ float g_fagg [P_TOT*D2];
__device__ float g_lfa  [P_TOT*DD];
__device__ float g_fx1  [(size_t)P_TOT*D2*KNN];
__device__ float g_G1   [(size_t)P_TOT*DD];
__device__ float g_G2   [(size_t)P_TOT*DD];

// ============================================================
// Kernel A: tiled transpose + mlp1 + G1 = f_pc @ fc1[:,:32]^T
// ============================================================
__global__ void __launch_bounds__(256) kA(const float* __restrict__ feature,
                                          const float* __restrict__ W,
                                          const float* __restrict__ s,
                                          const float* __restrict__ bvec,
                                          const float* __restrict__ fc1)
{
    __shared__ float Wt[CIN*CIN];
    __shared__ float sv[CIN], bv[CIN];
    __shared__ float fc1n[DD*CIN];
    __shared__ float tile[CIN][33];
    __shared__ float otile[CIN][33];
    __shared__ float gtile[DD][33];
    int tx = threadIdx.x, ty = threadIdx.y;
    int tid = ty*32 + tx;
    for (int i = tid; i < CIN*CIN; i += 256) { int o = i>>5, j = i&31; Wt[j*CIN+o] = W[i]; }
    for (int i = tid; i < DD*CIN; i += 256) { int o2 = i>>5, c = i&31; fc1n[o2*CIN + c] = fc1[o2*DD + c]; }
    if (ty == 0) { sv[tx] = s[tx]; bv[tx] = bvec[tx]; }

    int t = blockIdx.x;
    int b = t >> 9;
    int n0 = (t & 511) << 5;
    const float* fB = feature + (size_t)b*CIN*NPTS;
    #pragma unroll
    for (int i = 0; i < 32; i += 8)
        tile[ty+i][tx] = fB[(size_t)(ty+i)*NPTS + n0 + tx];
    __syncthreads();

    #pragma unroll
    for (int q = 0; q < 4; q++) {
        int o = ty + 8*q;
        float acc = 0.f;
        #pragma unroll
        for (int j = 0; j < CIN; j++) acc += Wt[j*CIN+o] * tile[j][tx];
        otile[o][tx] = fmaxf(acc*sv[o] + bv[o], 0.f);
    }
    __syncthreads();

    #pragma unroll
    for (int m = 0; m < 8; m++) {
        int o2 = ty + 8*m;
        float acc = 0.f;
        #pragma unroll
        for (int c = 0; c < CIN; c++) acc += fc1n[o2*CIN + c] * otile[c][tx];
        gtile[o2][tx] = acc;
    }
    __syncthreads();

    size_t pbase = (size_t)b*NPTS + n0;
    #pragma unroll
    for (int i = 0; i < 32; i += 8) {
        int r = ty + i;
        g_fpc  [(pbase + r)*CIN + tx] = otile[tx][r];
        g_featT[(pbase + r)*CIN + tx] = tile [tx][r];
    }
    #pragma unroll
    for (int j = 0; j < 8; j++) {
        int idx = tid + 256*j;
        int o2 = idx & 63, pl = idx >> 6;
        g_G1[(pbase + pl)*DD + o2] = gtile[o2][pl];
    }
}

// softmax over 16 + weighted aggregate
__device__ __forceinline__ float softagg(const float* a, const float* v) {
    float m = a[0];
    #pragma unroll
    for (int k = 1; k < 16; k++) m = fmaxf(m, a[k]);
    float se = 0.f, r = 0.f;
    #pragma unroll
    for (int k = 0; k < 16; k++) {
        float e = __expf(a[k] - m);
        se += e; r += e * v[k];
    }
    return __fdividef(r, se);
}

__device__ __forceinline__ void load_ids(const int* __restrict__ ip, int* ids)
{
    int4 i0 = ((const int4*)ip)[0];
    int4 i1 = ((const int4*)ip)[1];
    int4 i2 = ((const int4*)ip)[2];
    int4 i3 = ((const int4*)ip)[3];
    ids[0]=i0.x; ids[1]=i0.y; ids[2]=i0.z; ids[3]=i0.w;
    ids[4]=i1.x; ids[5]=i1.y; ids[6]=i1.z; ids[7]=i1.w;
    ids[8]=i2.x; ids[9]=i2.y; ids[10]=i2.z; ids[11]=i2.w;
    ids[12]=i3.x; ids[13]=i3.y; ids[14]=i3.z; ids[15]=i3.w;
}

__device__ __forceinline__ void bb1_math(const float* __restrict__ xyzB, int n,
                                         const int* ids,
                                         const float* w10, float bs, float bbv,
                                         float* fx)
{
    float cx = xyzB[n*3], cy = xyzB[n*3+1], cz = xyzB[n*3+2];
    float cpart = w10[4]*cx + w10[5]*cy + w10[6]*cz;
    #pragma unroll
    for (int k = 0; k < 16; k++) {
        int id = ids[k];
        float nx = xyzB[id*3], ny = xyzB[id*3+1], nz = xyzB[id*3+2];
        float rx = cx-nx, ry = cy-ny, rz = cz-nz;
        float d = sqrtf(rx*rx + ry*ry + rz*rz);
        float acc = cpart
                  + w10[0]*d  + w10[1]*rx + w10[2]*ry + w10[3]*rz
                  + w10[7]*nx + w10[8]*ny + w10[9]*nz;
        fx[k] = fmaxf(acc*bs + bbv, 0.f);
    }
}

// kB att: coalesced 4B weight reads + ALU pck.  fcT layout: [cc*64 + o].
__device__ __forceinline__ void att_half_T(const float* __restrict__ fcT,
                                           const float* __restrict__ xw, int lane,
                                           const float* g0, const float* g1,
                                           float* att0, float* att1)
{
    u64 acc0[8], acc1[8];
    #pragma unroll
    for (int q = 0; q < 8; q++) {
        acc0[q] = pck(g0[2*q], g0[2*q+1]);
        acc1[q] = pck(g1[2*q], g1[2*q+1]);
    }
    #pragma unroll 4
    for (int cc = 0; cc < 32; cc++) {
        float w0s = fcT[cc*DD + lane];
        float w1s = fcT[cc*DD + lane + 32];
        u64 w0 = pck(w0s, w0s);
        u64 w1 = pck(w1s, w1s);
        const ulonglong2* xv = (const ulonglong2*)&xw[cc*ST];
        #pragma unroll
        for (int q = 0; q < 4; q++) {
            ulonglong2 v = xv[q];
            acc0[2*q]   = fma2(w0, v.x, acc0[2*q]);
            acc0[2*q+1] = fma2(w0, v.y, acc0[2*q+1]);
            acc1[2*q]   = fma2(w1, v.x, acc1[2*q]);
            acc1[2*q+1] = fma2(w1, v.y, acc1[2*q+1]);
        }
    }
    #pragma unroll
    for (int q = 0; q < 8; q++) {
        float2 t0 = unpk(acc0[q]); att0[2*q] = t0.x; att0[2*q+1] = t0.y;
        float2 t1 = unpk(acc1[q]); att1[2*q] = t1.x; att1[2*q+1] = t1.y;
    }
}

// kC1 att: duplicated-pair weight reads.  wdup layout: [cc*128 + o*2 + h].
__device__ __forceinline__ void att_half_P(const float* __restrict__ wdup,
                                           const float* __restrict__ xw, int lane,
                                           const float* g0, const float* g1,
                                           float* att0, float* att1)
{
    u64 acc0[8], acc1[8];
    #pragma unroll
    for (int q = 0; q < 8; q++) {
        acc0[q] = pck(g0[2*q], g0[2*q+1]);
        acc1[q] = pck(g1[2*q], g1[2*q+1]);
    }
    #pragma unroll 4
    for (int cc = 0; cc < 32; cc++) {
        u64 w0 = *(const u64*)&wdup[cc*128 + lane*2];
        u64 w1 = *(const u64*)&wdup[cc*128 + (lane+32)*2];
        const ulonglong2* xv = (const ulonglong2*)&xw[cc*ST];
        #pragma unroll
        for (int q = 0; q < 4; q++) {
            ulonglong2 v = xv[q];
            acc0[2*q]   = fma2(w0, v.x, acc0[2*q]);
            acc0[2*q+1] = fma2(w0, v.y, acc0[2*q+1]);
            acc1[2*q]   = fma2(w1, v.x, acc1[2*q]);
            acc1[2*q+1] = fma2(w1, v.y, acc1[2*q+1]);
        }
    }
    #pragma unroll
    for (int q = 0; q < 8; q++) {
        float2 t0 = unpk(acc0[q]); att0[2*q] = t0.x; att0[2*q+1] = t0.y;
        float2 t1 = unpk(acc1[q]); att1[2*q] = t1.x; att1[2*q+1] = t1.y;
    }
}

// ============================================================
// Kernel B: stage-1 attention pooling -> g_fagg, caches bb1 -> g_fx1
// 192 threads (6 warps), 3 blocks/SM = 18 warps/SM.
// smem: fc1T[2048] | a1P[2048] | s1v/b1v[64] | x[6*640] = 32.0 KB
// ============================================================
#define SMEM_B_FLOATS (2048 + 2048 + 64 + WPB*D2*ST)

__global__ void __launch_bounds__(192, 3) kB(
    const float* __restrict__ xyz, const int* __restrict__ nidx,
    const float* __restrict__ bb1W, const float* __restrict__ bb1s, const float* __restrict__ bb1b,
    const float* __restrict__ fc1,  const float* __restrict__ a1W,
    const float* __restrict__ a1s,  const float* __restrict__ a1b)
{
    extern __shared__ float sm[];
    float* fc1T = sm;            // [cc*64 + o] = fc1[o*64 + 32+cc]
    float* a1P  = sm + 2048;     // [cc2*64 + o*2 + h]
    float* s1v  = sm + 4096;
    float* b1v  = sm + 4128;
    float* xball= sm + 4160;

    int tid = threadIdx.x;
    for (int i = tid; i < 2048; i += 192) { int cc = i>>6, o = i&63; fc1T[i] = fc1[o*DD + 32 + cc]; }
    for (int i = tid; i < 2048; i += 192) { int cc2 = i>>6, r = i&63; int o = r>>1, h = r&1;
                                            a1P[i] = a1W[o*DD + 2*cc2 + h]; }
    if (tid < 32) { s1v[tid] = a1s[tid]; b1v[tid] = a1b[tid]; }
    __syncthreads();

    int lane = tid & 31, w = tid >> 5;
    float* xw = xball + w*(D2*ST);
    float w10[10];
    #pragma unroll
    for (int j = 0; j < 10; j++) w10[j] = bb1W[lane*10 + j];
    float bs = bb1s[lane], bbv = bb1b[lane];

    int warpId = blockIdx.x*WPB + w;
    int nwarps = gridDim.x*WPB;
    for (int p = warpId; p < P_TOT; p += nwarps) {
        int b = p >> 14, n = p & (NPTS-1);
        const float* xyzB = xyz + (size_t)b*NPTS*3;
        const float* fpcB = g_fpc + (size_t)b*NPTS*CIN;
        const float* G1B  = g_G1  + (size_t)b*NPTS*DD;

        int ids[16];
        load_ids(nidx + (size_t)p*KNN, ids);
        float g0[16], g1[16];
        #pragma unroll
        for (int k = 0; k < 16; k++) {
            const float* gp = &G1B[(size_t)ids[k]*DD];
            g0[k] = gp[lane];
            g1[k] = gp[lane + 32];
        }
        float fn[16];
        #pragma unroll
        for (int k = 0; k < 16; k++) fn[k] = fpcB[(size_t)ids[k]*CIN + lane];

        float fx[16];
        bb1_math(xyzB, n, ids, w10, bs, bbv, fx);

        float* fxc = &g_fx1[(size_t)p*(D2*KNN) + lane*KNN];
        #pragma unroll
        for (int q = 0; q < 4; q++)
            *(float4*)&fxc[4*q] = make_float4(fx[4*q], fx[4*q+1], fx[4*q+2], fx[4*q+3]);

        float4* xr0 = (float4*)&xw[lane*ST];
        #pragma unroll
        for (int q = 0; q < 4; q++)
            xr0[q] = make_float4(fx[4*q], fx[4*q+1], fx[4*q+2], fx[4*q+3]);
        __syncwarp();

        float att0[16], att1[16];
        att_half_T(fc1T, xw, lane, g0, g1, att0, att1);

        float agg0 = softagg(att0, fn);
        float agg1 = softagg(att1, fx);
        __syncwarp();
        xw[lane] = agg0; xw[lane+32] = agg1;
        __syncwarp();

        u64 acc = 0ull, acc2 = 0ull;
        #pragma unroll
        for (int cc4 = 0; cc4 < 16; cc4++) {
            ulonglong2 xq = *(const ulonglong2*)&xw[4*cc4];
            acc  = fma2(*(const u64*)&a1P[(2*cc4)*64   + lane*2], xq.x, acc);
            acc2 = fma2(*(const u64*)&a1P[(2*cc4+1)*64 + lane*2], xq.y, acc2);
        }
        float2 t = unpk(acc), t2 = unpk(acc2);
        g_fagg[(size_t)p*D2 + lane] = fmaxf((t.x + t.y + t2.x + t2.y)*s1v[lane] + b1v[lane], 0.f);
        __syncwarp();
    }
}

// ============================================================
// Kernel G2: G2 = f_agg @ fc2[:, :32]^T  (warp-per-point)
// ============================================================
__global__ void __launch_bounds__(256) kG2(const float* __restrict__ fc2)
{
    __shared__ float w2P[16*128];
    __shared__ float sbuf[8][32];
    int tid = threadIdx.x;
    for (int i = tid; i < 16*128; i += 256) {
        int cc2 = i>>7, r = i&127; int o = r>>1, h = r&1;
        w2P[i] = fc2[o*DD + 2*cc2 + h];
    }
    __syncthreads();

    int lane = tid & 31, w = tid >> 5;
    float* sb = sbuf[w];
    int warpId = blockIdx.x*8 + w;
    int nwarps = gridDim.x*8;
    for (int p = warpId; p < P_TOT; p += nwarps) {
        sb[lane] = g_fagg[(size_t)p*D2 + lane];
        __syncwarp();
        u64 aA = 0ull, aB = 0ull;
        #pragma unroll
        for (int cc2 = 0; cc2 < 16; cc2++) {
            u64 xp = *(const u64*)&sb[2*cc2];
            aA = fma2(*(const u64*)&w2P[cc2*128 + lane*2], xp, aA);
            aB = fma2(*(const u64*)&w2P[cc2*128 + (lane+32)*2], xp, aB);
        }
        float2 tA = unpk(aA), tB = unpk(aB);
        g_G2[(size_t)p*DD + lane]      = tA.x + tA.y;
        g_G2[(size_t)p*DD + lane + 32] = tB.x + tB.y;
        __syncwarp();
    }
}

// ============================================================
// Kernel C1: stage-2 attention -> g_lfa [B,N,64]
// 192 threads (6 warps), 3 blocks/SM = 18 warps/SM.
// smem: bb2T[1024] | fc2P[4096] | a2P[8192] | a2s/b[128] | x[6*640] = 69.1 KB
// ============================================================
#define SMEM_C1_FLOATS (1024 + 4096 + 8192 + 128 + WPB*D2*ST)

__global__ void __launch_bounds__(192, 3) kC1(
    const int* __restrict__ nidx,
    const float* __restrict__ bb2W, const float* __restrict__ bb2s, const float* __restrict__ bb2b,
    const float* __restrict__ fc2,  const float* __restrict__ a2W,
    const float* __restrict__ a2s,  const float* __restrict__ a2b)
{
    extern __shared__ float sm[];
    float* bb2T = sm;             // [j*32 + c]
    float* fc2P = sm + 1024;      // [cc_rel*128 + o*2 + h]
    float* a2P  = sm + 5120;      // [cc2*128 + o*2 + h]
    float* a2sv = sm + 13312;
    float* a2bv = sm + 13376;
    float* xball= sm + 13440;

    int tid = threadIdx.x;
    for (int i = tid; i < 1024; i += 192) { int c = i>>5, j = i&31; bb2T[j*D2 + c] = bb2W[i]; }
    for (int i = tid; i < 4096; i += 192) { int cc = i>>7, o = (i&127)>>1; fc2P[i] = fc2[o*DD + 32 + cc]; }
    for (int i = tid; i < 8192; i += 192) { int cc2 = i>>7, r = i&127; int o = r>>1, h = r&1;
                                            a2P[i] = a2W[o*DD + 2*cc2 + h]; }
    for (int i = tid; i < DD; i += 192) { a2sv[i] = a2s[i]; a2bv[i] = a2b[i]; }
    __syncthreads();

    int lane = tid & 31, w = tid >> 5;
    float* xw = xball + w*(D2*ST);
    float bs2 = bb2s[lane], bb2v = bb2b[lane];

    int warpId = blockIdx.x*WPB + w;
    int nwarps = gridDim.x*WPB;
    for (int p = warpId; p < P_TOT; p += nwarps) {
        int b = p >> 14;
        const float* faggB = g_fagg + (size_t)b*NPTS*D2;
        const float* G2B   = g_G2   + (size_t)b*NPTS*DD;

        int ids[16];
        load_ids(nidx + (size_t)p*KNN, ids);
        float g0[16], g1[16];
        #pragma unroll
        for (int k = 0; k < 16; k++) {
            const float* gp = &G2B[(size_t)ids[k]*DD];
            g0[k] = gp[lane];
            g1[k] = gp[lane + 32];
        }
        float fn[16];
        #pragma unroll
        for (int k = 0; k < 16; k++) fn[k] = faggB[(size_t)ids[k]*D2 + lane];

        const float* fxc = &g_fx1[(size_t)p*(D2*KNN) + lane*KNN];
        float4* xr0 = (float4*)&xw[lane*ST];
        xr0[0] = *(const float4*)&fxc[0];
        xr0[1] = *(const float4*)&fxc[4];
        xr0[2] = *(const float4*)&fxc[8];
        xr0[3] = *(const float4*)&fxc[12];
        __syncwarp();

        u64 accx[8];
        #pragma unroll
        for (int q = 0; q < 8; q++) accx[q] = 0ull;
        #pragma unroll 4
        for (int j = 0; j < D2; j++) {
            float wv = bb2T[j*D2 + lane];
            u64 wj = pck(wv, wv);
            const ulonglong2* xv = (const ulonglong2*)&xw[j*ST];
            #pragma unroll
            for (int q = 0; q < 4; q++) {
                ulonglong2 v = xv[q];
                accx[2*q]   = fma2(wj, v.x, accx[2*q]);
                accx[2*q+1] = fma2(wj, v.y, accx[2*q+1]);
            }
        }
        float fx2[16];
        #pragma unroll
        for (int q = 0; q < 8; q++) {
            float2 t = unpk(accx[q]);
            fx2[2*q]   = fmaxf(t.x*bs2 + bb2v, 0.f);
            fx2[2*q+1] = fmaxf(t.y*bs2 + bb2v, 0.f);
        }
        __syncwarp();

        #pragma unroll
        for (int q = 0; q < 4; q++)
            xr0[q] = make_float4(fx2[4*q], fx2[4*q+1], fx2[4*q+2], fx2[4*q+3]);
        __syncwarp();

        float att0[16], att1[16];
        att_half_P(fc2P, xw, lane, g0, g1, att0, att1);

        float agg0 = softagg(att0, fn);
        float agg1 = softagg(att1, fx2);
        __syncwarp();
        xw[lane] = agg0; xw[lane+32] = agg1;
        __syncwarp();

        u64 aA = 0ull, aB = 0ull;
        #pragma unroll
        for (int cc2 = 0; cc2 < 32; cc2++) {
            u64 xp = *(const u64*)&xw[2*cc2];
            aA = fma2(*(const u64*)&a2P[cc2*128 + lane*2], xp, aA);
            aB = fma2(*(const u64*)&a2P[cc2*128 + (lane+32)*2], xp, aB);
        }
        float2 tA = unpk(aA), tB = unpk(aB);
        float* lp = g_lfa + (size_t)p*DD;
        lp[lane]      = fmaxf((tA.x + tA.y)*a2sv[lane]      + a2bv[lane],      0.f);
        lp[lane + 32] = fmaxf((tB.x + tB.y)*a2sv[lane + 32] + a2bv[lane + 32], 0.f);
        __syncwarp();
    }
}

// ============================================================
// Kernel C2: mlp2 + shortcut + leaky relu -> directly to out [B,128,N]
// ============================================================
#define C2_PTS 128
#define SMEM_C2_FLOATS (8192 + 4096 + 512)

__global__ void __launch_bounds__(256, 2) kC2(
    const float* __restrict__ m2W, const float* __restrict__ m2s, const float* __restrict__ m2b,
    const float* __restrict__ scW, const float* __restrict__ scs, const float* __restrict__ scb,
    float* __restrict__ out)
{
    extern __shared__ float sm[];
    float* m2T  = sm;
    float* scT  = sm + 8192;
    float* m2sv = sm + 12288;
    float* m2bv = sm + 12416;
    float* scsv = sm + 12544;
    float* scbv = sm + 12672;

    int tid = threadIdx.x;
    for (int i = tid; i < DOUT*DD; i += 256) m2T[i] = m2W[i];
    for (int i = tid; i < DOUT*D2; i += 256) scT[i] = scW[i];
    for (int i = tid; i < DOUT; i += 256) { m2sv[i] = m2s[i]; m2bv[i] = m2b[i];
                                            scsv[i] = scs[i]; scbv[i] = scb[i]; }
    __syncthreads();

    int pt   = tid & (C2_PTS-1);
    int half = tid >> 7;
    size_t p = (size_t)blockIdx.x * C2_PTS + pt;
    int b = (int)(p >> 14), n = (int)(p & (NPTS-1));

    u64 A[48];
    {
        const ulonglong2* lp = (const ulonglong2*)&g_lfa[p*DD];
        #pragma unroll
        for (int q = 0; q < 16; q++) { ulonglong2 v = lp[q]; A[2*q] = v.x; A[2*q+1] = v.y; }
        const ulonglong2* fp = (const ulonglong2*)&g_featT[p*CIN];
        #pragma unroll
        for (int q = 0; q < 8; q++) { ulonglong2 v = fp[q]; A[32+2*q] = v.x; A[32+2*q+1] = v.y; }
    }

    float* outB = out + ((size_t)b*DOUT + half*64)*NPTS + n;
    #pragma unroll 4
    for (int oc = 0; oc < 64; oc++) {
        int o = half*64 + oc;
        u64 acc0 = 0ull, acc1 = 0ull, acc2 = 0ull, acc3 = 0ull;
        const ulonglong2* wp = (const ulonglong2*)&m2T[o*DD];
        #pragma unroll
        for (int c = 0; c < 16; c++) {
            ulonglong2 wv = wp[c];
            acc0 = fma2(wv.x, A[2*c],   acc0);
            acc1 = fma2(wv.y, A[2*c+1], acc1);
        }
        const ulonglong2* sp = (const ulonglong2*)&scT[o*D2];
        #pragma unroll
        for (int j = 0; j < 8; j++) {
            ulonglong2 wv = sp[j];
            acc2 = fma2(wv.x, A[32+2*j],   acc2);
            acc3 = fma2(wv.y, A[32+2*j+1], acc3);
        }
        float2 t0 = unpk(acc0), t1 = unpk(acc1), t2 = unpk(acc2), t3 = unpk(acc3);
        float a  = (t0.x + t0.y + t1.x + t1.y)*m2sv[o] + m2bv[o];
        float sc = (t2.x + t2.y + t3.x + t3.y)*scsv[o] + scbv[o];
        float v = a + sc;
        outB[(size_t)oc*NPTS] = v > 0.f ? v : 0.2f*v;
    }
}

// ============================================================
extern "C" void kernel_launch(void* const* d_in, const int* in_sizes, int n_in,
                              void* d_out, int out_size)
{
    const float* feature = (const float*)d_in[0];
    const float* xyz     = (const float*)d_in[1];
    const int*   nidx    = (const int*)  d_in[2];
    const float* mlp1W = (const float*)d_in[3];
    const float* mlp1s = (const float*)d_in[4];
    const float* mlp1b = (const float*)d_in[5];
    const float* bb1W  = (const float*)d_in[6];
    const float* bb1s  = (const float*)d_in[7];
    const float* bb1b  = (const float*)d_in[8];
    const float* fc1   = (const float*)d_in[9];
    const float* a1W   = (const float*)d_in[10];
    const float* a1s   = (const float*)d_in[11];
    const float* a1b   = (const float*)d_in[12];
    const float* bb2W  = (const float*)d_in[13];
    const float* bb2s  = (const float*)d_in[14];
    const float* bb2b  = (const float*)d_in[15];
    const float* fc2   = (const float*)d_in[16];
    const float* a2W   = (const float*)d_in[17];
    const float* a2s   = (const float*)d_in[18];
    const float* a2b   = (const float*)d_in[19];
    const float* m2W   = (const float*)d_in[20];
    const float* m2s   = (const float*)d_in[21];
    const float* m2b   = (const float*)d_in[22];
    const float* scW   = (const float*)d_in[23];
    const float* scs   = (const float*)d_in[24];
    const float* scb   = (const float*)d_in[25];
    float* out = (float*)d_out;

    size_t smB  = SMEM_B_FLOATS  * sizeof(float);
    size_t smC1 = SMEM_C1_FLOATS * sizeof(float);
    size_t smC2 = SMEM_C2_FLOATS * sizeof(float);
    cudaFuncSetAttribute(kB,  cudaFuncAttributeMaxDynamicSharedMemorySize, (int)smB);
    cudaFuncSetAttribute(kC1, cudaFuncAttributeMaxDynamicSharedMemorySize, (int)smC1);
    cudaFuncSetAttribute(kC2, cudaFuncAttributeMaxDynamicSharedMemorySize, (int)smC2);

    kA<<<2048, dim3(32,8)>>>(feature, mlp1W, mlp1s, mlp1b, fc1);
    kB<<<444, 192, smB>>>(xyz, nidx, bb1W, bb1s, bb1b, fc1, a1W, a1s, a1b);
    kG2<<<512, 256>>>(fc2);
    kC1<<<444, 192, smC1>>>(nidx, bb2W, bb2s, bb2b, fc2, a2W, a2s, a2b);
    kC2<<<P_TOT/C2_PTS, 256, smC2>>>(m2W, m2s, m2b, scW, scs, scb, out);
}

// round 15
// speedup vs baseline: 1.0936x; 1.0936x over previous
#include <cuda_runtime.h>

#define BATCH 4
#define NPTS  16384
#define KNN   16
#define CIN   32
#define D2    32
#define DD    64
#define DOUT  128
#define P_TOT (BATCH*NPTS)
#define ST    20
#define WPB   8

typedef unsigned long long u64;

__device__ __forceinline__ u64 fma2(u64 a, u64 b, u64 c){
    u64 d; asm("fma.rn.f32x2 %0, %1, %2, %3;" : "=l"(d) : "l"(a), "l"(b), "l"(c)); return d;
}
__device__ __forceinline__ float2 unpk(u64 v){
    float2 f; asm("mov.b64 {%0, %1}, %2;" : "=f"(f.x), "=f"(f.y) : "l"(v)); return f;
}
__device__ __forceinline__ u64 pck(float x, float y){
    u64 v; asm("mov.b64 %0, {%1, %2};" : "=l"(v) : "f"(x), "f"(y)); return v;
}

// ---- scratch ----
__device__ float g_fpc  [P_TOT*CIN];
__device__ float g_featT[P_TOT*CIN];
__device__ float g_fagg [P_TOT*D2];
__device__ float g_lfa  [P_TOT*DD];
__device__ float g_fx1  [(size_t)P_TOT*D2*KNN];
__device__ float g_G1   [(size_t)P_TOT*DD];
__device__ float g_G2   [(size_t)P_TOT*DD];

// ============================================================
// Kernel A: tiled transpose + mlp1 + G1 = f_pc @ fc1[:,:32]^T
// ============================================================
__global__ void __launch_bounds__(256) kA(const float* __restrict__ feature,
                                          const float* __restrict__ W,
                                          const float* __restrict__ s,
                                          const float* __restrict__ bvec,
                                          const float* __restrict__ fc1)
{
    __shared__ float Wt[CIN*CIN];
    __shared__ float sv[CIN], bv[CIN];
    __shared__ float fc1n[DD*CIN];
    __shared__ float tile[CIN][33];
    __shared__ float otile[CIN][33];
    __shared__ float gtile[DD][33];
    int tx = threadIdx.x, ty = threadIdx.y;
    int tid = ty*32 + tx;
    for (int i = tid; i < CIN*CIN; i += 256) { int o = i>>5, j = i&31; Wt[j*CIN+o] = W[i]; }
    for (int i = tid; i < DD*CIN; i += 256) { int o2 = i>>5, c = i&31; fc1n[o2*CIN + c] = fc1[o2*DD + c]; }
    if (ty == 0) { sv[tx] = s[tx]; bv[tx] = bvec[tx]; }

    int t = blockIdx.x;
    int b = t >> 9;
    int n0 = (t & 511) << 5;
    const float* fB = feature + (size_t)b*CIN*NPTS;
    #pragma unroll
    for (int i = 0; i < 32; i += 8)
        tile[ty+i][tx] = fB[(size_t)(ty+i)*NPTS + n0 + tx];
    __syncthreads();

    #pragma unroll
    for (int q = 0; q < 4; q++) {
        int o = ty + 8*q;
        float acc = 0.f;
        #pragma unroll
        for (int j = 0; j < CIN; j++) acc += Wt[j*CIN+o] * tile[j][tx];
        otile[o][tx] = fmaxf(acc*sv[o] + bv[o], 0.f);
    }
    __syncthreads();

    #pragma unroll
    for (int m = 0; m < 8; m++) {
        int o2 = ty + 8*m;
        float acc = 0.f;
        #pragma unroll
        for (int c = 0; c < CIN; c++) acc += fc1n[o2*CIN + c] * otile[c][tx];
        gtile[o2][tx] = acc;
    }
    __syncthreads();

    size_t pbase = (size_t)b*NPTS + n0;
    #pragma unroll
    for (int i = 0; i < 32; i += 8) {
        int r = ty + i;
        g_fpc  [(pbase + r)*CIN + tx] = otile[tx][r];
        g_featT[(pbase + r)*CIN + tx] = tile [tx][r];
    }
    #pragma unroll
    for (int j = 0; j < 8; j++) {
        int idx = tid + 256*j;
        int o2 = idx & 63, pl = idx >> 6;
        g_G1[(pbase + pl)*DD + o2] = gtile[o2][pl];
    }
}

// softmax over 16 + weighted aggregate
__device__ __forceinline__ float softagg(const float* a, const float* v) {
    float m = a[0];
    #pragma unroll
    for (int k = 1; k < 16; k++) m = fmaxf(m, a[k]);
    float se = 0.f, r = 0.f;
    #pragma unroll
    for (int k = 0; k < 16; k++) {
        float e = __expf(a[k] - m);
        se += e; r += e * v[k];
    }
    return __fdividef(r, se);
}

__device__ __forceinline__ void load_ids(const int* __restrict__ ip, int* ids)
{
    int4 i0 = ((const int4*)ip)[0];
    int4 i1 = ((const int4*)ip)[1];
    int4 i2 = ((const int4*)ip)[2];
    int4 i3 = ((const int4*)ip)[3];
    ids[0]=i0.x; ids[1]=i0.y; ids[2]=i0.z; ids[3]=i0.w;
    ids[4]=i1.x; ids[5]=i1.y; ids[6]=i1.z; ids[7]=i1.w;
    ids[8]=i2.x; ids[9]=i2.y; ids[10]=i2.z; ids[11]=i2.w;
    ids[12]=i3.x; ids[13]=i3.y; ids[14]=i3.z; ids[15]=i3.w;
}

__device__ __forceinline__ void bb1_math(const float* __restrict__ xyzB, int n,
                                         const int* ids,
                                         const float* w10, float bs, float bbv,
                                         float* fx)
{
    float cx = xyzB[n*3], cy = xyzB[n*3+1], cz = xyzB[n*3+2];
    float cpart = w10[4]*cx + w10[5]*cy + w10[6]*cz;
    #pragma unroll
    for (int k = 0; k < 16; k++) {
        int id = ids[k];
        float nx = xyzB[id*3], ny = xyzB[id*3+1], nz = xyzB[id*3+2];
        float rx = cx-nx, ry = cy-ny, rz = cz-nz;
        float d = sqrtf(rx*rx + ry*ry + rz*rz);
        float acc = cpart
                  + w10[0]*d  + w10[1]*rx + w10[2]*ry + w10[3]*rz
                  + w10[7]*nx + w10[8]*ny + w10[9]*nz;
        fx[k] = fmaxf(acc*bs + bbv, 0.f);
    }
}

// kB att: coalesced 4B weight reads + ALU pck.  fcT layout: [cc*64 + o].
__device__ __forceinline__ void att_half_T(const float* __restrict__ fcT,
                                           const float* __restrict__ xw, int lane,
                                           const float* g0, const float* g1,
                                           float* att0, float* att1)
{
    u64 acc0[8], acc1[8];
    #pragma unroll
    for (int q = 0; q < 8; q++) {
        acc0[q] = pck(g0[2*q], g0[2*q+1]);
        acc1[q] = pck(g1[2*q], g1[2*q+1]);
    }
    #pragma unroll 4
    for (int cc = 0; cc < 32; cc++) {
        float w0s = fcT[cc*DD + lane];
        float w1s = fcT[cc*DD + lane + 32];
        u64 w0 = pck(w0s, w0s);
        u64 w1 = pck(w1s, w1s);
        const ulonglong2* xv = (const ulonglong2*)&xw[cc*ST];
        #pragma unroll
        for (int q = 0; q < 4; q++) {
            ulonglong2 v = xv[q];
            acc0[2*q]   = fma2(w0, v.x, acc0[2*q]);
            acc0[2*q+1] = fma2(w0, v.y, acc0[2*q+1]);
            acc1[2*q]   = fma2(w1, v.x, acc1[2*q]);
            acc1[2*q+1] = fma2(w1, v.y, acc1[2*q+1]);
        }
    }
    #pragma unroll
    for (int q = 0; q < 8; q++) {
        float2 t0 = unpk(acc0[q]); att0[2*q] = t0.x; att0[2*q+1] = t0.y;
        float2 t1 = unpk(acc1[q]); att1[2*q] = t1.x; att1[2*q+1] = t1.y;
    }
}

// kC1 att: duplicated-pair weight reads.  wdup layout: [cc*128 + o*2 + h].
__device__ __forceinline__ void att_half_P(const float* __restrict__ wdup,
                                           const float* __restrict__ xw, int lane,
                                           const float* g0, const float* g1,
                                           float* att0, float* att1)
{
    u64 acc0[8], acc1[8];
    #pragma unroll
    for (int q = 0; q < 8; q++) {
        acc0[q] = pck(g0[2*q], g0[2*q+1]);
        acc1[q] = pck(g1[2*q], g1[2*q+1]);
    }
    #pragma unroll 4
    for (int cc = 0; cc < 32; cc++) {
        u64 w0 = *(const u64*)&wdup[cc*128 + lane*2];
        u64 w1 = *(const u64*)&wdup[cc*128 + (lane+32)*2];
        const ulonglong2* xv = (const ulonglong2*)&xw[cc*ST];
        #pragma unroll
        for (int q = 0; q < 4; q++) {
            ulonglong2 v = xv[q];
            acc0[2*q]   = fma2(w0, v.x, acc0[2*q]);
            acc0[2*q+1] = fma2(w0, v.y, acc0[2*q+1]);
            acc1[2*q]   = fma2(w1, v.x, acc1[2*q]);
            acc1[2*q+1] = fma2(w1, v.y, acc1[2*q+1]);
        }
    }
    #pragma unroll
    for (int q = 0; q < 8; q++) {
        float2 t0 = unpk(acc0[q]); att0[2*q] = t0.x; att0[2*q+1] = t0.y;
        float2 t1 = unpk(acc1[q]); att1[2*q] = t1.x; att1[2*q+1] = t1.y;
    }
}

// ============================================================
// Kernel B: stage-1 attention pooling -> g_fagg + fused G2 epilogue -> g_G2
// 256 threads, (256,2).  smem: fc1T[2048] | a1P[2048] | w2P[2048] |
// s1v/b1v[64] | x[8*640] = 45.2 KB
// ============================================================
#define SMEM_B_FLOATS (2048 + 2048 + 2048 + 64 + WPB*D2*ST)

__global__ void __launch_bounds__(256) kB(
    const float* __restrict__ xyz, const int* __restrict__ nidx,
    const float* __restrict__ bb1W, const float* __restrict__ bb1s, const float* __restrict__ bb1b,
    const float* __restrict__ fc1,  const float* __restrict__ a1W,
    const float* __restrict__ a1s,  const float* __restrict__ a1b,
    const float* __restrict__ fc2)
{
    extern __shared__ float sm[];
    float* fc1T = sm;            // [cc*64 + o] = fc1[o*64 + 32+cc]
    float* a1P  = sm + 2048;     // [cc2*64 + o*2 + h]
    float* w2P  = sm + 4096;     // [c2*128 + o*2 + h] = fc2[o*64 + 2*c2 + h]
    float* s1v  = sm + 6144;
    float* b1v  = sm + 6176;
    float* xball= sm + 6208;

    int tid = threadIdx.x;
    for (int i = tid; i < 2048; i += 256) { int cc = i>>6, o = i&63; fc1T[i] = fc1[o*DD + 32 + cc]; }
    for (int i = tid; i < 2048; i += 256) { int cc2 = i>>6, r = i&63; int o = r>>1, h = r&1;
                                            a1P[i] = a1W[o*DD + 2*cc2 + h]; }
    for (int i = tid; i < 2048; i += 256) { int c2 = i>>7, r = i&127; int o = r>>1, h = r&1;
                                            w2P[i] = fc2[o*DD + 2*c2 + h]; }
    if (tid < 32) { s1v[tid] = a1s[tid]; b1v[tid] = a1b[tid]; }
    __syncthreads();

    int lane = tid & 31, w = tid >> 5;
    float* xw = xball + w*(D2*ST);
    float w10[10];
    #pragma unroll
    for (int j = 0; j < 10; j++) w10[j] = bb1W[lane*10 + j];
    float bs = bb1s[lane], bbv = bb1b[lane];

    int warpId = blockIdx.x*WPB + w;
    int nwarps = gridDim.x*WPB;
    for (int p = warpId; p < P_TOT; p += nwarps) {
        int b = p >> 14, n = p & (NPTS-1);
        const float* xyzB = xyz + (size_t)b*NPTS*3;
        const float* fpcB = g_fpc + (size_t)b*NPTS*CIN;
        const float* G1B  = g_G1  + (size_t)b*NPTS*DD;

        int ids[16];
        load_ids(nidx + (size_t)p*KNN, ids);
        float g0[16], g1[16];
        #pragma unroll
        for (int k = 0; k < 16; k++) {
            const float* gp = &G1B[(size_t)ids[k]*DD];
            g0[k] = gp[lane];
            g1[k] = gp[lane + 32];
        }
        float fn[16];
        #pragma unroll
        for (int k = 0; k < 16; k++) fn[k] = fpcB[(size_t)ids[k]*CIN + lane];

        float fx[16];
        bb1_math(xyzB, n, ids, w10, bs, bbv, fx);

        float* fxc = &g_fx1[(size_t)p*(D2*KNN) + lane*KNN];
        #pragma unroll
        for (int q = 0; q < 4; q++)
            *(float4*)&fxc[4*q] = make_float4(fx[4*q], fx[4*q+1], fx[4*q+2], fx[4*q+3]);

        float4* xr0 = (float4*)&xw[lane*ST];
        #pragma unroll
        for (int q = 0; q < 4; q++)
            xr0[q] = make_float4(fx[4*q], fx[4*q+1], fx[4*q+2], fx[4*q+3]);
        __syncwarp();

        float att0[16], att1[16];
        att_half_T(fc1T, xw, lane, g0, g1, att0, att1);

        float agg0 = softagg(att0, fn);
        float agg1 = softagg(att1, fx);
        __syncwarp();
        xw[lane] = agg0; xw[lane+32] = agg1;
        __syncwarp();

        // a1 @ agg -> fagg
        u64 acc = 0ull, acc2 = 0ull;
        #pragma unroll
        for (int cc4 = 0; cc4 < 16; cc4++) {
            ulonglong2 xq = *(const ulonglong2*)&xw[4*cc4];
            acc  = fma2(*(const u64*)&a1P[(2*cc4)*64   + lane*2], xq.x, acc);
            acc2 = fma2(*(const u64*)&a1P[(2*cc4+1)*64 + lane*2], xq.y, acc2);
        }
        float2 t = unpk(acc), t2 = unpk(acc2);
        float f = fmaxf((t.x + t.y + t2.x + t2.y)*s1v[lane] + b1v[lane], 0.f);
        g_fagg[(size_t)p*D2 + lane] = f;
        __syncwarp();
        xw[lane] = f;                 // stage fagg for the G2 epilogue
        __syncwarp();

        // fused kG2: G2 = fagg @ fc2[:, :32]^T (same op order as old kG2)
        u64 aA = 0ull, aB = 0ull;
        #pragma unroll
        for (int c2 = 0; c2 < 16; c2++) {
            u64 xp = *(const u64*)&xw[2*c2];
            aA = fma2(*(const u64*)&w2P[c2*128 + lane*2], xp, aA);
            aB = fma2(*(const u64*)&w2P[c2*128 + (lane+32)*2], xp, aB);
        }
        float2 tA = unpk(aA), tB = unpk(aB);
        g_G2[(size_t)p*DD + lane]      = tA.x + tA.y;
        g_G2[(size_t)p*DD + lane + 32] = tB.x + tB.y;
        __syncwarp();
    }
}

// ============================================================
// Kernel C1 (R12/R7 best variant): stage-2 attention -> g_lfa [B,N,64]
// smem: bb2T[1024] | fc2P[4096] | a2P[8192] | a2s/b[128] | x[8*640] = 74.2 KB
// ============================================================
#define SMEM_C1_FLOATS (1024 + 4096 + 8192 + 128 + WPB*D2*ST)

__global__ void __launch_bounds__(256) kC1(
    const int* __restrict__ nidx,
    const float* __restrict__ bb2W, const float* __restrict__ bb2s, const float* __restrict__ bb2b,
    const float* __restrict__ fc2,  const float* __restrict__ a2W,
    const float* __restrict__ a2s,  const float* __restrict__ a2b)
{
    extern __shared__ float sm[];
    float* bb2T = sm;             // [j*32 + c]
    float* fc2P = sm + 1024;      // [cc_rel*128 + o*2 + h]
    float* a2P  = sm + 5120;      // [cc2*128 + o*2 + h]
    float* a2sv = sm + 13312;
    float* a2bv = sm + 13376;
    float* xball= sm + 13440;

    int tid = threadIdx.x;
    for (int i = tid; i < 1024; i += 256) { int c = i>>5, j = i&31; bb2T[j*D2 + c] = bb2W[i]; }
    for (int i = tid; i < 4096; i += 256) { int cc = i>>7, o = (i&127)>>1; fc2P[i] = fc2[o*DD + 32 + cc]; }
    for (int i = tid; i < 8192; i += 256) { int cc2 = i>>7, r = i&127; int o = r>>1, h = r&1;
                                            a2P[i] = a2W[o*DD + 2*cc2 + h]; }
    for (int i = tid; i < DD; i += 256) { a2sv[i] = a2s[i]; a2bv[i] = a2b[i]; }
    __syncthreads();

    int lane = tid & 31, w = tid >> 5;
    float* xw = xball + w*(D2*ST);
    float bs2 = bb2s[lane], bb2v = bb2b[lane];

    int warpId = blockIdx.x*WPB + w;
    int nwarps = gridDim.x*WPB;
    for (int p = warpId; p < P_TOT; p += nwarps) {
        int b = p >> 14;
        const float* faggB = g_fagg + (size_t)b*NPTS*D2;
        const float* G2B   = g_G2   + (size_t)b*NPTS*DD;

        int ids[16];
        load_ids(nidx + (size_t)p*KNN, ids);
        float g0[16], g1[16];
        #pragma unroll
        for (int k = 0; k < 16; k++) {
            const float* gp = &G2B[(size_t)ids[k]*DD];
            g0[k] = gp[lane];
            g1[k] = gp[lane + 32];
        }
        float fn[16];
        #pragma unroll
        for (int k = 0; k < 16; k++) fn[k] = faggB[(size_t)ids[k]*D2 + lane];

        const float* fxc = &g_fx1[(size_t)p*(D2*KNN) + lane*KNN];
        float4* xr0 = (float4*)&xw[lane*ST];
        xr0[0] = *(const float4*)&fxc[0];
        xr0[1] = *(const float4*)&fxc[4];
        xr0[2] = *(const float4*)&fxc[8];
        xr0[3] = *(const float4*)&fxc[12];
        __syncwarp();

        u64 accx[8];
        #pragma unroll
        for (int q = 0; q < 8; q++) accx[q] = 0ull;
        #pragma unroll 4
        for (int j = 0; j < D2; j++) {
            float wv = bb2T[j*D2 + lane];
            u64 wj = pck(wv, wv);
            const ulonglong2* xv = (const ulonglong2*)&xw[j*ST];
            #pragma unroll
            for (int q = 0; q < 4; q++) {
                ulonglong2 v = xv[q];
                accx[2*q]   = fma2(wj, v.x, accx[2*q]);
                accx[2*q+1] = fma2(wj, v.y, accx[2*q+1]);
            }
        }
        float fx2[16];
        #pragma unroll
        for (int q = 0; q < 8; q++) {
            float2 t = unpk(accx[q]);
            fx2[2*q]   = fmaxf(t.x*bs2 + bb2v, 0.f);
            fx2[2*q+1] = fmaxf(t.y*bs2 + bb2v, 0.f);
        }
        __syncwarp();

        #pragma unroll
        for (int q = 0; q < 4; q++)
            xr0[q] = make_float4(fx2[4*q], fx2[4*q+1], fx2[4*q+2], fx2[4*q+3]);
        __syncwarp();

        float att0[16], att1[16];
        att_half_P(fc2P, xw, lane, g0, g1, att0, att1);

        float agg0 = softagg(att0, fn);
        float agg1 = softagg(att1, fx2);
        __syncwarp();
        xw[lane] = agg0; xw[lane+32] = agg1;
        __syncwarp();

        u64 aA = 0ull, aB = 0ull;
        #pragma unroll
        for (int cc2 = 0; cc2 < 32; cc2++) {
            u64 xp = *(const u64*)&xw[2*cc2];
            aA = fma2(*(const u64*)&a2P[cc2*128 + lane*2], xp, aA);
            aB = fma2(*(const u64*)&a2P[cc2*128 + (lane+32)*2], xp, aB);
        }
        float2 tA = unpk(aA), tB = unpk(aB);
        float* lp = g_lfa + (size_t)p*DD;
        lp[lane]      = fmaxf((tA.x + tA.y)*a2sv[lane]      + a2bv[lane],      0.f);
        lp[lane + 32] = fmaxf((tB.x + tB.y)*a2sv[lane + 32] + a2bv[lane + 32], 0.f);
        __syncwarp();
    }
}

// ============================================================
// Kernel C2: mlp2 + shortcut + leaky relu -> directly to out [B,128,N]
// ============================================================
#define C2_PTS 128
#define SMEM_C2_FLOATS (8192 + 4096 + 512)

__global__ void __launch_bounds__(256, 2) kC2(
    const float* __restrict__ m2W, const float* __restrict__ m2s, const float* __restrict__ m2b,
    const float* __restrict__ scW, const float* __restrict__ scs, const float* __restrict__ scb,
    float* __restrict__ out)
{
    extern __shared__ float sm[];
    float* m2T  = sm;
    float* scT  = sm + 8192;
    float* m2sv = sm + 12288;
    float* m2bv = sm + 12416;
    float* scsv = sm + 12544;
    float* scbv = sm + 12672;

    int tid = threadIdx.x;
    for (int i = tid; i < DOUT*DD; i += 256) m2T[i] = m2W[i];
    for (int i = tid; i < DOUT*D2; i += 256) scT[i] = scW[i];
    for (int i = tid; i < DOUT; i += 256) { m2sv[i] = m2s[i]; m2bv[i] = m2b[i];
                                            scsv[i] = scs[i]; scbv[i] = scb[i]; }
    __syncthreads();

    int pt   = tid & (C2_PTS-1);
    int half = tid >> 7;
    size_t p = (size_t)blockIdx.x * C2_PTS + pt;
    int b = (int)(p >> 14), n = (int)(p & (NPTS-1));

    u64 A[48];
    {
        const ulonglong2* lp = (const ulonglong2*)&g_lfa[p*DD];
        #pragma unroll
        for (int q = 0; q < 16; q++) { ulonglong2 v = lp[q]; A[2*q] = v.x; A[2*q+1] = v.y; }
        const ulonglong2* fp = (const ulonglong2*)&g_featT[p*CIN];
        #pragma unroll
        for (int q = 0; q < 8; q++) { ulonglong2 v = fp[q]; A[32+2*q] = v.x; A[32+2*q+1] = v.y; }
    }

    float* outB = out + ((size_t)b*DOUT + half*64)*NPTS + n;
    #pragma unroll 4
    for (int oc = 0; oc < 64; oc++) {
        int o = half*64 + oc;
        u64 acc0 = 0ull, acc1 = 0ull, acc2 = 0ull, acc3 = 0ull;
        const ulonglong2* wp = (const ulonglong2*)&m2T[o*DD];
        #pragma unroll
        for (int c = 0; c < 16; c++) {
            ulonglong2 wv = wp[c];
            acc0 = fma2(wv.x, A[2*c],   acc0);
            acc1 = fma2(wv.y, A[2*c+1], acc1);
        }
        const ulonglong2* sp = (const ulonglong2*)&scT[o*D2];
        #pragma unroll
        for (int j = 0; j < 8; j++) {
            ulonglong2 wv = sp[j];
            acc2 = fma2(wv.x, A[32+2*j],   acc2);
            acc3 = fma2(wv.y, A[32+2*j+1], acc3);
        }
        float2 t0 = unpk(acc0), t1 = unpk(acc1), t2 = unpk(acc2), t3 = unpk(acc3);
        float a  = (t0.x + t0.y + t1.x + t1.y)*m2sv[o] + m2bv[o];
        float sc = (t2.x + t2.y + t3.x + t3.y)*scsv[o] + scbv[o];
        float v = a + sc;
        outB[(size_t)oc*NPTS] = v > 0.f ? v : 0.2f*v;
    }
}

// ============================================================
extern "C" void kernel_launch(void* const* d_in, const int* in_sizes, int n_in,
                              void* d_out, int out_size)
{
    const float* feature = (const float*)d_in[0];
    const float* xyz     = (const float*)d_in[1];
    const int*   nidx    = (const int*)  d_in[2];
    const float* mlp1W = (const float*)d_in[3];
    const float* mlp1s = (const float*)d_in[4];
    const float* mlp1b = (const float*)d_in[5];
    const float* bb1W  = (const float*)d_in[6];
    const float* bb1s  = (const float*)d_in[7];
    const float* bb1b  = (const float*)d_in[8];
    const float* fc1   = (const float*)d_in[9];
    const float* a1W   = (const float*)d_in[10];
    const float* a1s   = (const float*)d_in[11];
    const float* a1b   = (const float*)d_in[12];
    const float* bb2W  = (const float*)d_in[13];
    const float* bb2s  = (const float*)d_in[14];
    const float* bb2b  = (const float*)d_in[15];
    const float* fc2   = (const float*)d_in[16];
    const float* a2W   = (const float*)d_in[17];
    const float* a2s   = (const float*)d_in[18];
    const float* a2b   = (const float*)d_in[19];
    const float* m2W   = (const float*)d_in[20];
    const float* m2s   = (const float*)d_in[21];
    const float* m2b   = (const float*)d_in[22];
    const float* scW   = (const float*)d_in[23];
    const float* scs   = (const float*)d_in[24];
    const float* scb   = (const float*)d_in[25];
    float* out = (float*)d_out;

    size_t smB  = SMEM_B_FLOATS  * sizeof(float);
    size_t smC1 = SMEM_C1_FLOATS * sizeof(float);
    size_t smC2 = SMEM_C2_FLOATS * sizeof(float);
    cudaFuncSetAttribute(kB,  cudaFuncAttributeMaxDynamicSharedMemorySize, (int)smB);
    cudaFuncSetAttribute(kC1, cudaFuncAttributeMaxDynamicSharedMemorySize, (int)smC1);
    cudaFuncSetAttribute(kC2, cudaFuncAttributeMaxDynamicSharedMemorySize, (int)smC2);

    kA<<<2048, dim3(32,8)>>>(feature, mlp1W, mlp1s, mlp1b, fc1);
    kB<<<296, 256, smB>>>(xyz, nidx, bb1W, bb1s, bb1b, fc1, a1W, a1s, a1b, fc2);
    kC1<<<296, 256, smC1>>>(nidx, bb2W, bb2s, bb2b, fc2, a2W, a2s, a2b);
    kC2<<<P_TOT/C2_PTS, 256, smC2>>>(m2W, m2s, m2b, scW, scs, scb, out);
}

// round 16
// speedup vs baseline: 1.0948x; 1.0011x over previous
#include <cuda_runtime.h>

#define BATCH 4
#define NPTS  16384
#define KNN   16
#define CIN   32
#define D2    32
#define DD    64
#define DOUT  128
#define P_TOT (BATCH*NPTS)
#define ST    20
#define WPB   8

typedef unsigned long long u64;

__device__ __forceinline__ u64 fma2(u64 a, u64 b, u64 c){
    u64 d; asm("fma.rn.f32x2 %0, %1, %2, %3;" : "=l"(d) : "l"(a), "l"(b), "l"(c)); return d;
}
__device__ __forceinline__ float2 unpk(u64 v){
    float2 f; asm("mov.b64 {%0, %1}, %2;" : "=f"(f.x), "=f"(f.y) : "l"(v)); return f;
}
__device__ __forceinline__ u64 pck(float x, float y){
    u64 v; asm("mov.b64 %0, {%1, %2};" : "=l"(v) : "f"(x), "f"(y)); return v;
}

// ---- scratch ----
__device__ float g_fpc  [P_TOT*CIN];
__device__ float g_featT[P_TOT*CIN];
__device__ float g_fagg [P_TOT*D2];
__device__ float g_lfa  [P_TOT*DD];
__device__ float g_fx1  [(size_t)P_TOT*D2*KNN];
__device__ float g_G1   [(size_t)P_TOT*DD];
__device__ float g_G2   [(size_t)P_TOT*DD];

// ============================================================
// Kernel A: tiled transpose + mlp1 + G1 = f_pc @ fc1[:,:32]^T
// ============================================================
__global__ void __launch_bounds__(256) kA(const float* __restrict__ feature,
                                          const float* __restrict__ W,
                                          const float* __restrict__ s,
                                          const float* __restrict__ bvec,
                                          const float* __restrict__ fc1)
{
    __shared__ float Wt[CIN*CIN];
    __shared__ float sv[CIN], bv[CIN];
    __shared__ float fc1n[DD*CIN];
    __shared__ float tile[CIN][33];
    __shared__ float otile[CIN][33];
    __shared__ float gtile[DD][33];
    int tx = threadIdx.x, ty = threadIdx.y;
    int tid = ty*32 + tx;
    for (int i = tid; i < CIN*CIN; i += 256) { int o = i>>5, j = i&31; Wt[j*CIN+o] = W[i]; }
    for (int i = tid; i < DD*CIN; i += 256) { int o2 = i>>5, c = i&31; fc1n[o2*CIN + c] = fc1[o2*DD + c]; }
    if (ty == 0) { sv[tx] = s[tx]; bv[tx] = bvec[tx]; }

    int t = blockIdx.x;
    int b = t >> 9;
    int n0 = (t & 511) << 5;
    const float* fB = feature + (size_t)b*CIN*NPTS;
    #pragma unroll
    for (int i = 0; i < 32; i += 8)
        tile[ty+i][tx] = fB[(size_t)(ty+i)*NPTS + n0 + tx];
    __syncthreads();

    #pragma unroll
    for (int q = 0; q < 4; q++) {
        int o = ty + 8*q;
        float acc = 0.f;
        #pragma unroll
        for (int j = 0; j < CIN; j++) acc += Wt[j*CIN+o] * tile[j][tx];
        otile[o][tx] = fmaxf(acc*sv[o] + bv[o], 0.f);
    }
    __syncthreads();

    #pragma unroll
    for (int m = 0; m < 8; m++) {
        int o2 = ty + 8*m;
        float acc = 0.f;
        #pragma unroll
        for (int c = 0; c < CIN; c++) acc += fc1n[o2*CIN + c] * otile[c][tx];
        gtile[o2][tx] = acc;
    }
    __syncthreads();

    size_t pbase = (size_t)b*NPTS + n0;
    #pragma unroll
    for (int i = 0; i < 32; i += 8) {
        int r = ty + i;
        g_fpc  [(pbase + r)*CIN + tx] = otile[tx][r];
        g_featT[(pbase + r)*CIN + tx] = tile [tx][r];
    }
    #pragma unroll
    for (int j = 0; j < 8; j++) {
        int idx = tid + 256*j;
        int o2 = idx & 63, pl = idx >> 6;
        g_G1[(pbase + pl)*DD + o2] = gtile[o2][pl];
    }
}

// softmax over 16 + weighted aggregate
__device__ __forceinline__ float softagg(const float* a, const float* v) {
    float m = a[0];
    #pragma unroll
    for (int k = 1; k < 16; k++) m = fmaxf(m, a[k]);
    float se = 0.f, r = 0.f;
    #pragma unroll
    for (int k = 0; k < 16; k++) {
        float e = __expf(a[k] - m);
        se += e; r += e * v[k];
    }
    return __fdividef(r, se);
}

__device__ __forceinline__ void load_ids(const int* __restrict__ ip, int* ids)
{
    int4 i0 = ((const int4*)ip)[0];
    int4 i1 = ((const int4*)ip)[1];
    int4 i2 = ((const int4*)ip)[2];
    int4 i3 = ((const int4*)ip)[3];
    ids[0]=i0.x; ids[1]=i0.y; ids[2]=i0.z; ids[3]=i0.w;
    ids[4]=i1.x; ids[5]=i1.y; ids[6]=i1.z; ids[7]=i1.w;
    ids[8]=i2.x; ids[9]=i2.y; ids[10]=i2.z; ids[11]=i2.w;
    ids[12]=i3.x; ids[13]=i3.y; ids[14]=i3.z; ids[15]=i3.w;
}

__device__ __forceinline__ void bb1_math(const float* __restrict__ xyzB, int n,
                                         const int* ids,
                                         const float* w10, float bs, float bbv,
                                         float* fx)
{
    float cx = xyzB[n*3], cy = xyzB[n*3+1], cz = xyzB[n*3+2];
    float cpart = w10[4]*cx + w10[5]*cy + w10[6]*cz;
    #pragma unroll
    for (int k = 0; k < 16; k++) {
        int id = ids[k];
        float nx = xyzB[id*3], ny = xyzB[id*3+1], nz = xyzB[id*3+2];
        float rx = cx-nx, ry = cy-ny, rz = cz-nz;
        float d = sqrtf(rx*rx + ry*ry + rz*rz);
        float acc = cpart
                  + w10[0]*d  + w10[1]*rx + w10[2]*ry + w10[3]*rz
                  + w10[7]*nx + w10[8]*ny + w10[9]*nz;
        fx[k] = fmaxf(acc*bs + bbv, 0.f);
    }
}

// kB att: coalesced 4B weight reads + ALU pck.  fcT layout: [cc*64 + o].
__device__ __forceinline__ void att_half_T(const float* __restrict__ fcT,
                                           const float* __restrict__ xw, int lane,
                                           const float* g0, const float* g1,
                                           float* att0, float* att1)
{
    u64 acc0[8], acc1[8];
    #pragma unroll
    for (int q = 0; q < 8; q++) {
        acc0[q] = pck(g0[2*q], g0[2*q+1]);
        acc1[q] = pck(g1[2*q], g1[2*q+1]);
    }
    #pragma unroll 4
    for (int cc = 0; cc < 32; cc++) {
        float w0s = fcT[cc*DD + lane];
        float w1s = fcT[cc*DD + lane + 32];
        u64 w0 = pck(w0s, w0s);
        u64 w1 = pck(w1s, w1s);
        const ulonglong2* xv = (const ulonglong2*)&xw[cc*ST];
        #pragma unroll
        for (int q = 0; q < 4; q++) {
            ulonglong2 v = xv[q];
            acc0[2*q]   = fma2(w0, v.x, acc0[2*q]);
            acc0[2*q+1] = fma2(w0, v.y, acc0[2*q+1]);
            acc1[2*q]   = fma2(w1, v.x, acc1[2*q]);
            acc1[2*q+1] = fma2(w1, v.y, acc1[2*q+1]);
        }
    }
    #pragma unroll
    for (int q = 0; q < 8; q++) {
        float2 t0 = unpk(acc0[q]); att0[2*q] = t0.x; att0[2*q+1] = t0.y;
        float2 t1 = unpk(acc1[q]); att1[2*q] = t1.x; att1[2*q+1] = t1.y;
    }
}

// kC1 att: duplicated-pair weight reads.  wdup layout: [cc*128 + o*2 + h].
__device__ __forceinline__ void att_half_P(const float* __restrict__ wdup,
                                           const float* __restrict__ xw, int lane,
                                           const float* g0, const float* g1,
                                           float* att0, float* att1)
{
    u64 acc0[8], acc1[8];
    #pragma unroll
    for (int q = 0; q < 8; q++) {
        acc0[q] = pck(g0[2*q], g0[2*q+1]);
        acc1[q] = pck(g1[2*q], g1[2*q+1]);
    }
    #pragma unroll 4
    for (int cc = 0; cc < 32; cc++) {
        u64 w0 = *(const u64*)&wdup[cc*128 + lane*2];
        u64 w1 = *(const u64*)&wdup[cc*128 + (lane+32)*2];
        const ulonglong2* xv = (const ulonglong2*)&xw[cc*ST];
        #pragma unroll
        for (int q = 0; q < 4; q++) {
            ulonglong2 v = xv[q];
            acc0[2*q]   = fma2(w0, v.x, acc0[2*q]);
            acc0[2*q+1] = fma2(w0, v.y, acc0[2*q+1]);
            acc1[2*q]   = fma2(w1, v.x, acc1[2*q]);
            acc1[2*q+1] = fma2(w1, v.y, acc1[2*q+1]);
        }
    }
    #pragma unroll
    for (int q = 0; q < 8; q++) {
        float2 t0 = unpk(acc0[q]); att0[2*q] = t0.x; att0[2*q+1] = t0.y;
        float2 t1 = unpk(acc1[q]); att1[2*q] = t1.x; att1[2*q+1] = t1.y;
    }
}

// ============================================================
// Kernel B: stage-1 attention pooling -> g_fagg + fused G2 epilogue -> g_G2
// ============================================================
#define SMEM_B_FLOATS (2048 + 2048 + 2048 + 64 + WPB*D2*ST)

__global__ void __launch_bounds__(256) kB(
    const float* __restrict__ xyz, const int* __restrict__ nidx,
    const float* __restrict__ bb1W, const float* __restrict__ bb1s, const float* __restrict__ bb1b,
    const float* __restrict__ fc1,  const float* __restrict__ a1W,
    const float* __restrict__ a1s,  const float* __restrict__ a1b,
    const float* __restrict__ fc2)
{
    extern __shared__ float sm[];
    float* fc1T = sm;            // [cc*64 + o] = fc1[o*64 + 32+cc]
    float* a1P  = sm + 2048;     // [cc2*64 + o*2 + h]
    float* w2P  = sm + 4096;     // [c2*128 + o*2 + h] = fc2[o*64 + 2*c2 + h]
    float* s1v  = sm + 6144;
    float* b1v  = sm + 6176;
    float* xball= sm + 6208;

    int tid = threadIdx.x;
    for (int i = tid; i < 2048; i += 256) { int cc = i>>6, o = i&63; fc1T[i] = fc1[o*DD + 32 + cc]; }
    for (int i = tid; i < 2048; i += 256) { int cc2 = i>>6, r = i&63; int o = r>>1, h = r&1;
                                            a1P[i] = a1W[o*DD + 2*cc2 + h]; }
    for (int i = tid; i < 2048; i += 256) { int c2 = i>>7, r = i&127; int o = r>>1, h = r&1;
                                            w2P[i] = fc2[o*DD + 2*c2 + h]; }
    if (tid < 32) { s1v[tid] = a1s[tid]; b1v[tid] = a1b[tid]; }
    __syncthreads();

    int lane = tid & 31, w = tid >> 5;
    float* xw = xball + w*(D2*ST);
    float w10[10];
    #pragma unroll
    for (int j = 0; j < 10; j++) w10[j] = bb1W[lane*10 + j];
    float bs = bb1s[lane], bbv = bb1b[lane];

    int warpId = blockIdx.x*WPB + w;
    int nwarps = gridDim.x*WPB;
    for (int p = warpId; p < P_TOT; p += nwarps) {
        int b = p >> 14, n = p & (NPTS-1);
        const float* xyzB = xyz + (size_t)b*NPTS*3;
        const float* fpcB = g_fpc + (size_t)b*NPTS*CIN;
        const float* G1B  = g_G1  + (size_t)b*NPTS*DD;

        int ids[16];
        load_ids(nidx + (size_t)p*KNN, ids);
        float g0[16], g1[16];
        #pragma unroll
        for (int k = 0; k < 16; k++) {
            const float* gp = &G1B[(size_t)ids[k]*DD];
            g0[k] = gp[lane];
            g1[k] = gp[lane + 32];
        }
        float fn[16];
        #pragma unroll
        for (int k = 0; k < 16; k++) fn[k] = fpcB[(size_t)ids[k]*CIN + lane];

        float fx[16];
        bb1_math(xyzB, n, ids, w10, bs, bbv, fx);

        float* fxc = &g_fx1[(size_t)p*(D2*KNN) + lane*KNN];
        #pragma unroll
        for (int q = 0; q < 4; q++)
            *(float4*)&fxc[4*q] = make_float4(fx[4*q], fx[4*q+1], fx[4*q+2], fx[4*q+3]);

        float4* xr0 = (float4*)&xw[lane*ST];
        #pragma unroll
        for (int q = 0; q < 4; q++)
            xr0[q] = make_float4(fx[4*q], fx[4*q+1], fx[4*q+2], fx[4*q+3]);
        __syncwarp();

        float att0[16], att1[16];
        att_half_T(fc1T, xw, lane, g0, g1, att0, att1);

        float agg0 = softagg(att0, fn);
        float agg1 = softagg(att1, fx);
        __syncwarp();
        xw[lane] = agg0; xw[lane+32] = agg1;
        __syncwarp();

        // a1 @ agg -> fagg
        u64 acc = 0ull, acc2 = 0ull;
        #pragma unroll
        for (int cc4 = 0; cc4 < 16; cc4++) {
            ulonglong2 xq = *(const ulonglong2*)&xw[4*cc4];
            acc  = fma2(*(const u64*)&a1P[(2*cc4)*64   + lane*2], xq.x, acc);
            acc2 = fma2(*(const u64*)&a1P[(2*cc4+1)*64 + lane*2], xq.y, acc2);
        }
        float2 t = unpk(acc), t2 = unpk(acc2);
        float f = fmaxf((t.x + t.y + t2.x + t2.y)*s1v[lane] + b1v[lane], 0.f);
        g_fagg[(size_t)p*D2 + lane] = f;
        __syncwarp();
        xw[lane] = f;                 // stage fagg for the G2 epilogue
        __syncwarp();

        // fused kG2: G2 = fagg @ fc2[:, :32]^T
        u64 aA = 0ull, aB = 0ull;
        #pragma unroll
        for (int c2 = 0; c2 < 16; c2++) {
            u64 xp = *(const u64*)&xw[2*c2];
            aA = fma2(*(const u64*)&w2P[c2*128 + lane*2], xp, aA);
            aB = fma2(*(const u64*)&w2P[c2*128 + (lane+32)*2], xp, aB);
        }
        float2 tA = unpk(aA), tB = unpk(aB);
        g_G2[(size_t)p*DD + lane]      = tA.x + tA.y;
        g_G2[(size_t)p*DD + lane + 32] = tB.x + tB.y;
        __syncwarp();
    }
}

// ============================================================
// Kernel C1 (best variant): stage-2 attention -> g_lfa [B,N,64]
// ============================================================
#define SMEM_C1_FLOATS (1024 + 4096 + 8192 + 128 + WPB*D2*ST)

__global__ void __launch_bounds__(256) kC1(
    const int* __restrict__ nidx,
    const float* __restrict__ bb2W, const float* __restrict__ bb2s, const float* __restrict__ bb2b,
    const float* __restrict__ fc2,  const float* __restrict__ a2W,
    const float* __restrict__ a2s,  const float* __restrict__ a2b)
{
    extern __shared__ float sm[];
    float* bb2T = sm;             // [j*32 + c]
    float* fc2P = sm + 1024;      // [cc_rel*128 + o*2 + h]
    float* a2P  = sm + 5120;      // [cc2*128 + o*2 + h]
    float* a2sv = sm + 13312;
    float* a2bv = sm + 13376;
    float* xball= sm + 13440;

    int tid = threadIdx.x;
    for (int i = tid; i < 1024; i += 256) { int c = i>>5, j = i&31; bb2T[j*D2 + c] = bb2W[i]; }
    for (int i = tid; i < 4096; i += 256) { int cc = i>>7, o = (i&127)>>1; fc2P[i] = fc2[o*DD + 32 + cc]; }
    for (int i = tid; i < 8192; i += 256) { int cc2 = i>>7, r = i&127; int o = r>>1, h = r&1;
                                            a2P[i] = a2W[o*DD + 2*cc2 + h]; }
    for (int i = tid; i < DD; i += 256) { a2sv[i] = a2s[i]; a2bv[i] = a2b[i]; }
    __syncthreads();

    int lane = tid & 31, w = tid >> 5;
    float* xw = xball + w*(D2*ST);
    float bs2 = bb2s[lane], bb2v = bb2b[lane];

    int warpId = blockIdx.x*WPB + w;
    int nwarps = gridDim.x*WPB;
    for (int p = warpId; p < P_TOT; p += nwarps) {
        int b = p >> 14;
        const float* faggB = g_fagg + (size_t)b*NPTS*D2;
        const float* G2B   = g_G2   + (size_t)b*NPTS*DD;

        int ids[16];
        load_ids(nidx + (size_t)p*KNN, ids);
        float g0[16], g1[16];
        #pragma unroll
        for (int k = 0; k < 16; k++) {
            const float* gp = &G2B[(size_t)ids[k]*DD];
            g0[k] = gp[lane];
            g1[k] = gp[lane + 32];
        }
        float fn[16];
        #pragma unroll
        for (int k = 0; k < 16; k++) fn[k] = faggB[(size_t)ids[k]*D2 + lane];

        const float* fxc = &g_fx1[(size_t)p*(D2*KNN) + lane*KNN];
        float4* xr0 = (float4*)&xw[lane*ST];
        xr0[0] = *(const float4*)&fxc[0];
        xr0[1] = *(const float4*)&fxc[4];
        xr0[2] = *(const float4*)&fxc[8];
        xr0[3] = *(const float4*)&fxc[12];
        __syncwarp();

        u64 accx[8];
        #pragma unroll
        for (int q = 0; q < 8; q++) accx[q] = 0ull;
        #pragma unroll 4
        for (int j = 0; j < D2; j++) {
            float wv = bb2T[j*D2 + lane];
            u64 wj = pck(wv, wv);
            const ulonglong2* xv = (const ulonglong2*)&xw[j*ST];
            #pragma unroll
            for (int q = 0; q < 4; q++) {
                ulonglong2 v = xv[q];
                accx[2*q]   = fma2(wj, v.x, accx[2*q]);
                accx[2*q+1] = fma2(wj, v.y, accx[2*q+1]);
            }
        }
        float fx2[16];
        #pragma unroll
        for (int q = 0; q < 8; q++) {
            float2 t = unpk(accx[q]);
            fx2[2*q]   = fmaxf(t.x*bs2 + bb2v, 0.f);
            fx2[2*q+1] = fmaxf(t.y*bs2 + bb2v, 0.f);
        }
        __syncwarp();

        #pragma unroll
        for (int q = 0; q < 4; q++)
            xr0[q] = make_float4(fx2[4*q], fx2[4*q+1], fx2[4*q+2], fx2[4*q+3]);
        __syncwarp();

        float att0[16], att1[16];
        att_half_P(fc2P, xw, lane, g0, g1, att0, att1);

        float agg0 = softagg(att0, fn);
        float agg1 = softagg(att1, fx2);
        __syncwarp();
        xw[lane] = agg0; xw[lane+32] = agg1;
        __syncwarp();

        u64 aA = 0ull, aB = 0ull;
        #pragma unroll
        for (int cc2 = 0; cc2 < 32; cc2++) {
            u64 xp = *(const u64*)&xw[2*cc2];
            aA = fma2(*(const u64*)&a2P[cc2*128 + lane*2], xp, aA);
            aB = fma2(*(const u64*)&a2P[cc2*128 + (lane+32)*2], xp, aB);
        }
        float2 tA = unpk(aA), tB = unpk(aB);
        float* lp = g_lfa + (size_t)p*DD;
        lp[lane]      = fmaxf((tA.x + tA.y)*a2sv[lane]      + a2bv[lane],      0.f);
        lp[lane + 32] = fmaxf((tB.x + tB.y)*a2sv[lane + 32] + a2bv[lane + 32], 0.f);
        __syncwarp();
    }
}

// ============================================================
// Kernel C2 v5: mlp2 + shortcut + leaky relu -> out [B,128,N]
// Activations staged via smem: coalesced LDG + low-conflict LDS.
// smem: m2T[8192] | scT[4096] | scales[512] | act[128*98] = 101.4 KB
// (256,2): 2 blocks/SM, 16 warps/SM.
// ============================================================
#define C2_PTS 128
#define ACT_ST 98    // 392B rows: u64-aligned, bank stride 2 -> 2-way conflicts
#define SMEM_C2_FLOATS (8192 + 4096 + 512 + C2_PTS*ACT_ST)

__global__ void __launch_bounds__(256, 2) kC2(
    const float* __restrict__ m2W, const float* __restrict__ m2s, const float* __restrict__ m2b,
    const float* __restrict__ scW, const float* __restrict__ scs, const float* __restrict__ scb,
    float* __restrict__ out)
{
    extern __shared__ float sm[];
    float* m2T  = sm;
    float* scT  = sm + 8192;
    float* m2sv = sm + 12288;
    float* m2bv = sm + 12416;
    float* scsv = sm + 12544;
    float* scbv = sm + 12672;
    float* act  = sm + 12800;   // [pt*ACT_ST + c]

    int tid = threadIdx.x;
    for (int i = tid; i < DOUT*DD; i += 256) m2T[i] = m2W[i];
    for (int i = tid; i < DOUT*D2; i += 256) scT[i] = scW[i];
    for (int i = tid; i < DOUT; i += 256) { m2sv[i] = m2s[i]; m2bv[i] = m2b[i];
                                            scsv[i] = scs[i]; scbv[i] = scb[i]; }

    int p0 = blockIdx.x * C2_PTS;
    // stage activations: perfectly coalesced LDG.128, float2 STS
    for (int i = tid; i < C2_PTS*16; i += 256) {
        int pt = i >> 4, q = i & 15;
        float4 v = *(const float4*)&g_lfa[(size_t)(p0 + pt)*DD + 4*q];
        float* dst = &act[pt*ACT_ST + 4*q];
        *(float2*)dst       = make_float2(v.x, v.y);
        *(float2*)(dst + 2) = make_float2(v.z, v.w);
    }
    for (int i = tid; i < C2_PTS*8; i += 256) {
        int pt = i >> 3, q = i & 7;
        float4 v = *(const float4*)&g_featT[(size_t)(p0 + pt)*CIN + 4*q];
        float* dst = &act[pt*ACT_ST + 64 + 4*q];
        *(float2*)dst       = make_float2(v.x, v.y);
        *(float2*)(dst + 2) = make_float2(v.z, v.w);
    }
    __syncthreads();

    int pt   = tid & (C2_PTS-1);
    int half = tid >> 7;
    size_t p = (size_t)p0 + pt;
    int b = (int)(p >> 14), n = (int)(p & (NPTS-1));

    u64 A[48];
    {
        const float* arow = &act[pt*ACT_ST];
        #pragma unroll
        for (int r = 0; r < 48; r++) A[r] = *(const u64*)&arow[2*r];
    }

    float* outB = out + ((size_t)b*DOUT + half*64)*NPTS + n;
    #pragma unroll 4
    for (int oc = 0; oc < 64; oc++) {
        int o = half*64 + oc;
        u64 acc0 = 0ull, acc1 = 0ull, acc2 = 0ull, acc3 = 0ull;
        const ulonglong2* wp = (const ulonglong2*)&m2T[o*DD];
        #pragma unroll
        for (int c = 0; c < 16; c++) {
            ulonglong2 wv = wp[c];
            acc0 = fma2(wv.x, A[2*c],   acc0);
            acc1 = fma2(wv.y, A[2*c+1], acc1);
        }
        const ulonglong2* sp = (const ulonglong2*)&scT[o*D2];
        #pragma unroll
        for (int j = 0; j < 8; j++) {
            ulonglong2 wv = sp[j];
            acc2 = fma2(wv.x, A[32+2*j],   acc2);
            acc3 = fma2(wv.y, A[32+2*j+1], acc3);
        }
        float2 t0 = unpk(acc0), t1 = unpk(acc1), t2 = unpk(acc2), t3 = unpk(acc3);
        float a  = (t0.x + t0.y + t1.x + t1.y)*m2sv[o] + m2bv[o];
        float sc = (t2.x + t2.y + t3.x + t3.y)*scsv[o] + scbv[o];
        float v = a + sc;
        outB[(size_t)oc*NPTS] = v > 0.f ? v : 0.2f*v;
    }
}

// ============================================================
extern "C" void kernel_launch(void* const* d_in, const int* in_sizes, int n_in,
                              void* d_out, int out_size)
{
    const float* feature = (const float*)d_in[0];
    const float* xyz     = (const float*)d_in[1];
    const int*   nidx    = (const int*)  d_in[2];
    const float* mlp1W = (const float*)d_in[3];
    const float* mlp1s = (const float*)d_in[4];
    const float* mlp1b = (const float*)d_in[5];
    const float* bb1W  = (const float*)d_in[6];
    const float* bb1s  = (const float*)d_in[7];
    const float* bb1b  = (const float*)d_in[8];
    const float* fc1   = (const float*)d_in[9];
    const float* a1W   = (const float*)d_in[10];
    const float* a1s   = (const float*)d_in[11];
    const float* a1b   = (const float*)d_in[12];
    const float* bb2W  = (const float*)d_in[13];
    const float* bb2s  = (const float*)d_in[14];
    const float* bb2b  = (const float*)d_in[15];
    const float* fc2   = (const float*)d_in[16];
    const float* a2W   = (const float*)d_in[17];
    const float* a2s   = (const float*)d_in[18];
    const float* a2b   = (const float*)d_in[19];
    const float* m2W   = (const float*)d_in[20];
    const float* m2s   = (const float*)d_in[21];
    const float* m2b   = (const float*)d_in[22];
    const float* scW   = (const float*)d_in[23];
    const float* scs   = (const float*)d_in[24];
    const float* scb   = (const float*)d_in[25];
    float* out = (float*)d_out;

    size_t smB  = SMEM_B_FLOATS  * sizeof(float);
    size_t smC1 = SMEM_C1_FLOATS * sizeof(float);
    size_t smC2 = SMEM_C2_FLOATS * sizeof(float);
    cudaFuncSetAttribute(kB,  cudaFuncAttributeMaxDynamicSharedMemorySize, (int)smB);
    cudaFuncSetAttribute(kC1, cudaFuncAttributeMaxDynamicSharedMemorySize, (int)smC1);
    cudaFuncSetAttribute(kC2, cudaFuncAttributeMaxDynamicSharedMemorySize, (int)smC2);

    kA<<<2048, dim3(32,8)>>>(feature, mlp1W, mlp1s, mlp1b, fc1);
    kB<<<296, 256, smB>>>(xyz, nidx, bb1W, bb1s, bb1b, fc1, a1W, a1s, a1b, fc2);
    kC1<<<296, 256, smC1>>>(nidx, bb2W, bb2s, bb2b, fc2, a2W, a2s, a2b);
    kC2<<<P_TOT/C2_PTS, 256, smC2>>>(m2W, m2s, m2b, scW, scs, scb, out);
}

// round 17
// speedup vs baseline: 1.1103x; 1.0142x over previous
#include <cuda_runtime.h>

#define BATCH 4
#define NPTS  16384
#define KNN   16
#define CIN   32
#define D2    32
#define DD    64
#define DOUT  128
#define P_TOT (BATCH*NPTS)
#define ST    20
#define WPB   8

typedef unsigned long long u64;

__device__ __forceinline__ u64 fma2(u64 a, u64 b, u64 c){
    u64 d; asm("fma.rn.f32x2 %0, %1, %2, %3;" : "=l"(d) : "l"(a), "l"(b), "l"(c)); return d;
}
__device__ __forceinline__ float2 unpk(u64 v){
    float2 f; asm("mov.b64 {%0, %1}, %2;" : "=f"(f.x), "=f"(f.y) : "l"(v)); return f;
}
__device__ __forceinline__ u64 pck(float x, float y){
    u64 v; asm("mov.b64 %0, {%1, %2};" : "=l"(v) : "f"(x), "f"(y)); return v;
}

// ---- scratch ----
__device__ float g_fpc  [P_TOT*CIN];
__device__ float g_featT[P_TOT*CIN];
__device__ float g_fagg [P_TOT*D2];
__device__ float g_lfa  [P_TOT*DD];
__device__ float g_fx1  [(size_t)P_TOT*D2*KNN];
__device__ float g_G1   [(size_t)P_TOT*DD];
__device__ float g_G2   [(size_t)P_TOT*DD];

// ============================================================
// Kernel A: tiled transpose + mlp1 + G1 = f_pc @ fc1[:,:32]^T
// ============================================================
__global__ void __launch_bounds__(256) kA(const float* __restrict__ feature,
                                          const float* __restrict__ W,
                                          const float* __restrict__ s,
                                          const float* __restrict__ bvec,
                                          const float* __restrict__ fc1)
{
    __shared__ float Wt[CIN*CIN];
    __shared__ float sv[CIN], bv[CIN];
    __shared__ float fc1n[DD*CIN];
    __shared__ float tile[CIN][33];
    __shared__ float otile[CIN][33];
    __shared__ float gtile[DD][33];
    int tx = threadIdx.x, ty = threadIdx.y;
    int tid = ty*32 + tx;
    for (int i = tid; i < CIN*CIN; i += 256) { int o = i>>5, j = i&31; Wt[j*CIN+o] = W[i]; }
    for (int i = tid; i < DD*CIN; i += 256) { int o2 = i>>5, c = i&31; fc1n[o2*CIN + c] = fc1[o2*DD + c]; }
    if (ty == 0) { sv[tx] = s[tx]; bv[tx] = bvec[tx]; }

    int t = blockIdx.x;
    int b = t >> 9;
    int n0 = (t & 511) << 5;
    const float* fB = feature + (size_t)b*CIN*NPTS;
    #pragma unroll
    for (int i = 0; i < 32; i += 8)
        tile[ty+i][tx] = fB[(size_t)(ty+i)*NPTS + n0 + tx];
    __syncthreads();

    #pragma unroll
    for (int q = 0; q < 4; q++) {
        int o = ty + 8*q;
        float acc = 0.f;
        #pragma unroll
        for (int j = 0; j < CIN; j++) acc += Wt[j*CIN+o] * tile[j][tx];
        otile[o][tx] = fmaxf(acc*sv[o] + bv[o], 0.f);
    }
    __syncthreads();

    #pragma unroll
    for (int m = 0; m < 8; m++) {
        int o2 = ty + 8*m;
        float acc = 0.f;
        #pragma unroll
        for (int c = 0; c < CIN; c++) acc += fc1n[o2*CIN + c] * otile[c][tx];
        gtile[o2][tx] = acc;
    }
    __syncthreads();

    size_t pbase = (size_t)b*NPTS + n0;
    #pragma unroll
    for (int i = 0; i < 32; i += 8) {
        int r = ty + i;
        g_fpc  [(pbase + r)*CIN + tx] = otile[tx][r];
        g_featT[(pbase + r)*CIN + tx] = tile [tx][r];
    }
    #pragma unroll
    for (int j = 0; j < 8; j++) {
        int idx = tid + 256*j;
        int o2 = idx & 63, pl = idx >> 6;
        g_G1[(pbase + pl)*DD + o2] = gtile[o2][pl];
    }
}

// softmax over 16 + weighted aggregate
__device__ __forceinline__ float softagg(const float* a, const float* v) {
    float m = a[0];
    #pragma unroll
    for (int k = 1; k < 16; k++) m = fmaxf(m, a[k]);
    float se = 0.f, r = 0.f;
    #pragma unroll
    for (int k = 0; k < 16; k++) {
        float e = __expf(a[k] - m);
        se += e; r += e * v[k];
    }
    return __fdividef(r, se);
}

__device__ __forceinline__ void load_ids(const int* __restrict__ ip, int* ids)
{
    int4 i0 = ((const int4*)ip)[0];
    int4 i1 = ((const int4*)ip)[1];
    int4 i2 = ((const int4*)ip)[2];
    int4 i3 = ((const int4*)ip)[3];
    ids[0]=i0.x; ids[1]=i0.y; ids[2]=i0.z; ids[3]=i0.w;
    ids[4]=i1.x; ids[5]=i1.y; ids[6]=i1.z; ids[7]=i1.w;
    ids[8]=i2.x; ids[9]=i2.y; ids[10]=i2.z; ids[11]=i2.w;
    ids[12]=i3.x; ids[13]=i3.y; ids[14]=i3.z; ids[15]=i3.w;
}

__device__ __forceinline__ void bb1_math(const float* __restrict__ xyzB, int n,
                                         const int* ids,
                                         const float* w10, float bs, float bbv,
                                         float* fx)
{
    float cx = xyzB[n*3], cy = xyzB[n*3+1], cz = xyzB[n*3+2];
    float cpart = w10[4]*cx + w10[5]*cy + w10[6]*cz;
    #pragma unroll
    for (int k = 0; k < 16; k++) {
        int id = ids[k];
        float nx = xyzB[id*3], ny = xyzB[id*3+1], nz = xyzB[id*3+2];
        float rx = cx-nx, ry = cy-ny, rz = cz-nz;
        float d = sqrtf(rx*rx + ry*ry + rz*rz);
        float acc = cpart
                  + w10[0]*d  + w10[1]*rx + w10[2]*ry + w10[3]*rz
                  + w10[7]*nx + w10[8]*ny + w10[9]*nz;
        fx[k] = fmaxf(acc*bs + bbv, 0.f);
    }
}

// kB att: coalesced 4B weight reads + ALU pck.  fcT layout: [cc*64 + o].
__device__ __forceinline__ void att_half_T(const float* __restrict__ fcT,
                                           const float* __restrict__ xw, int lane,
                                           const float* g0, const float* g1,
                                           float* att0, float* att1)
{
    u64 acc0[8], acc1[8];
    #pragma unroll
    for (int q = 0; q < 8; q++) {
        acc0[q] = pck(g0[2*q], g0[2*q+1]);
        acc1[q] = pck(g1[2*q], g1[2*q+1]);
    }
    #pragma unroll 4
    for (int cc = 0; cc < 32; cc++) {
        float w0s = fcT[cc*DD + lane];
        float w1s = fcT[cc*DD + lane + 32];
        u64 w0 = pck(w0s, w0s);
        u64 w1 = pck(w1s, w1s);
        const ulonglong2* xv = (const ulonglong2*)&xw[cc*ST];
        #pragma unroll
        for (int q = 0; q < 4; q++) {
            ulonglong2 v = xv[q];
            acc0[2*q]   = fma2(w0, v.x, acc0[2*q]);
            acc0[2*q+1] = fma2(w0, v.y, acc0[2*q+1]);
            acc1[2*q]   = fma2(w1, v.x, acc1[2*q]);
            acc1[2*q+1] = fma2(w1, v.y, acc1[2*q+1]);
        }
    }
    #pragma unroll
    for (int q = 0; q < 8; q++) {
        float2 t0 = unpk(acc0[q]); att0[2*q] = t0.x; att0[2*q+1] = t0.y;
        float2 t1 = unpk(acc1[q]); att1[2*q] = t1.x; att1[2*q+1] = t1.y;
    }
}

// kC1 att: duplicated-pair weight reads.  wdup layout: [cc*128 + o*2 + h].
__device__ __forceinline__ void att_half_P(const float* __restrict__ wdup,
                                           const float* __restrict__ xw, int lane,
                                           const float* g0, const float* g1,
                                           float* att0, float* att1)
{
    u64 acc0[8], acc1[8];
    #pragma unroll
    for (int q = 0; q < 8; q++) {
        acc0[q] = pck(g0[2*q], g0[2*q+1]);
        acc1[q] = pck(g1[2*q], g1[2*q+1]);
    }
    #pragma unroll 4
    for (int cc = 0; cc < 32; cc++) {
        u64 w0 = *(const u64*)&wdup[cc*128 + lane*2];
        u64 w1 = *(const u64*)&wdup[cc*128 + (lane+32)*2];
        const ulonglong2* xv = (const ulonglong2*)&xw[cc*ST];
        #pragma unroll
        for (int q = 0; q < 4; q++) {
            ulonglong2 v = xv[q];
            acc0[2*q]   = fma2(w0, v.x, acc0[2*q]);
            acc0[2*q+1] = fma2(w0, v.y, acc0[2*q+1]);
            acc1[2*q]   = fma2(w1, v.x, acc1[2*q]);
            acc1[2*q+1] = fma2(w1, v.y, acc1[2*q+1]);
        }
    }
    #pragma unroll
    for (int q = 0; q < 8; q++) {
        float2 t0 = unpk(acc0[q]); att0[2*q] = t0.x; att0[2*q+1] = t0.y;
        float2 t1 = unpk(acc1[q]); att1[2*q] = t1.x; att1[2*q+1] = t1.y;
    }
}

// ============================================================
// Kernel B: stage-1 attention pooling -> g_fagg + fused G2 epilogue -> g_G2
// ============================================================
#define SMEM_B_FLOATS (2048 + 2048 + 2048 + 64 + WPB*D2*ST)

__global__ void __launch_bounds__(256) kB(
    const float* __restrict__ xyz, const int* __restrict__ nidx,
    const float* __restrict__ bb1W, const float* __restrict__ bb1s, const float* __restrict__ bb1b,
    const float* __restrict__ fc1,  const float* __restrict__ a1W,
    const float* __restrict__ a1s,  const float* __restrict__ a1b,
    const float* __restrict__ fc2)
{
    extern __shared__ float sm[];
    float* fc1T = sm;            // [cc*64 + o] = fc1[o*64 + 32+cc]
    float* a1P  = sm + 2048;     // [cc2*64 + o*2 + h]
    float* w2P  = sm + 4096;     // [c2*128 + o*2 + h] = fc2[o*64 + 2*c2 + h]
    float* s1v  = sm + 6144;
    float* b1v  = sm + 6176;
    float* xball= sm + 6208;

    int tid = threadIdx.x;
    for (int i = tid; i < 2048; i += 256) { int cc = i>>6, o = i&63; fc1T[i] = fc1[o*DD + 32 + cc]; }
    for (int i = tid; i < 2048; i += 256) { int cc2 = i>>6, r = i&63; int o = r>>1, h = r&1;
                                            a1P[i] = a1W[o*DD + 2*cc2 + h]; }
    for (int i = tid; i < 2048; i += 256) { int c2 = i>>7, r = i&127; int o = r>>1, h = r&1;
                                            w2P[i] = fc2[o*DD + 2*c2 + h]; }
    if (tid < 32) { s1v[tid] = a1s[tid]; b1v[tid] = a1b[tid]; }
    __syncthreads();

    int lane = tid & 31, w = tid >> 5;
    float* xw = xball + w*(D2*ST);
    float w10[10];
    #pragma unroll
    for (int j = 0; j < 10; j++) w10[j] = bb1W[lane*10 + j];
    float bs = bb1s[lane], bbv = bb1b[lane];

    int warpId = blockIdx.x*WPB + w;
    int nwarps = gridDim.x*WPB;
    for (int p = warpId; p < P_TOT; p += nwarps) {
        int b = p >> 14, n = p & (NPTS-1);
        const float* xyzB = xyz + (size_t)b*NPTS*3;
        const float* fpcB = g_fpc + (size_t)b*NPTS*CIN;
        const float* G1B  = g_G1  + (size_t)b*NPTS*DD;

        int ids[16];
        load_ids(nidx + (size_t)p*KNN, ids);
        float g0[16], g1[16];
        #pragma unroll
        for (int k = 0; k < 16; k++) {
            const float* gp = &G1B[(size_t)ids[k]*DD];
            g0[k] = gp[lane];
            g1[k] = gp[lane + 32];
        }
        float fn[16];
        #pragma unroll
        for (int k = 0; k < 16; k++) fn[k] = fpcB[(size_t)ids[k]*CIN + lane];

        float fx[16];
        bb1_math(xyzB, n, ids, w10, bs, bbv, fx);

        float* fxc = &g_fx1[(size_t)p*(D2*KNN) + lane*KNN];
        #pragma unroll
        for (int q = 0; q < 4; q++)
            *(float4*)&fxc[4*q] = make_float4(fx[4*q], fx[4*q+1], fx[4*q+2], fx[4*q+3]);

        float4* xr0 = (float4*)&xw[lane*ST];
        #pragma unroll
        for (int q = 0; q < 4; q++)
            xr0[q] = make_float4(fx[4*q], fx[4*q+1], fx[4*q+2], fx[4*q+3]);
        __syncwarp();

        float att0[16], att1[16];
        att_half_T(fc1T, xw, lane, g0, g1, att0, att1);

        float agg0 = softagg(att0, fn);
        float agg1 = softagg(att1, fx);
        __syncwarp();
        xw[lane] = agg0; xw[lane+32] = agg1;
        __syncwarp();

        // a1 @ agg -> fagg
        u64 acc = 0ull, acc2 = 0ull;
        #pragma unroll
        for (int cc4 = 0; cc4 < 16; cc4++) {
            ulonglong2 xq = *(const ulonglong2*)&xw[4*cc4];
            acc  = fma2(*(const u64*)&a1P[(2*cc4)*64   + lane*2], xq.x, acc);
            acc2 = fma2(*(const u64*)&a1P[(2*cc4+1)*64 + lane*2], xq.y, acc2);
        }
        float2 t = unpk(acc), t2 = unpk(acc2);
        float f = fmaxf((t.x + t.y + t2.x + t2.y)*s1v[lane] + b1v[lane], 0.f);
        g_fagg[(size_t)p*D2 + lane] = f;
        __syncwarp();
        xw[lane] = f;                 // stage fagg for the G2 epilogue
        __syncwarp();

        // fused kG2: G2 = fagg @ fc2[:, :32]^T
        u64 aA = 0ull, aB = 0ull;
        #pragma unroll
        for (int c2 = 0; c2 < 16; c2++) {
            u64 xp = *(const u64*)&xw[2*c2];
            aA = fma2(*(const u64*)&w2P[c2*128 + lane*2], xp, aA);
            aB = fma2(*(const u64*)&w2P[c2*128 + (lane+32)*2], xp, aB);
        }
        float2 tA = unpk(aA), tB = unpk(aB);
        g_G2[(size_t)p*DD + lane]      = tA.x + tA.y;
        g_G2[(size_t)p*DD + lane + 32] = tB.x + tB.y;
        __syncwarp();
    }
}

// ============================================================
// Kernel C1 (best variant): stage-2 attention -> g_lfa [B,N,64]
// ============================================================
#define SMEM_C1_FLOATS (1024 + 4096 + 8192 + 128 + WPB*D2*ST)

__global__ void __launch_bounds__(256) kC1(
    const int* __restrict__ nidx,
    const float* __restrict__ bb2W, const float* __restrict__ bb2s, const float* __restrict__ bb2b,
    const float* __restrict__ fc2,  const float* __restrict__ a2W,
    const float* __restrict__ a2s,  const float* __restrict__ a2b)
{
    extern __shared__ float sm[];
    float* bb2T = sm;             // [j*32 + c]
    float* fc2P = sm + 1024;      // [cc_rel*128 + o*2 + h]
    float* a2P  = sm + 5120;      // [cc2*128 + o*2 + h]
    float* a2sv = sm + 13312;
    float* a2bv = sm + 13376;
    float* xball= sm + 13440;

    int tid = threadIdx.x;
    for (int i = tid; i < 1024; i += 256) { int c = i>>5, j = i&31; bb2T[j*D2 + c] = bb2W[i]; }
    for (int i = tid; i < 4096; i += 256) { int cc = i>>7, o = (i&127)>>1; fc2P[i] = fc2[o*DD + 32 + cc]; }
    for (int i = tid; i < 8192; i += 256) { int cc2 = i>>7, r = i&127; int o = r>>1, h = r&1;
                                            a2P[i] = a2W[o*DD + 2*cc2 + h]; }
    for (int i = tid; i < DD; i += 256) { a2sv[i] = a2s[i]; a2bv[i] = a2b[i]; }
    __syncthreads();

    int lane = tid & 31, w = tid >> 5;
    float* xw = xball + w*(D2*ST);
    float bs2 = bb2s[lane], bb2v = bb2b[lane];

    int warpId = blockIdx.x*WPB + w;
    int nwarps = gridDim.x*WPB;
    for (int p = warpId; p < P_TOT; p += nwarps) {
        int b = p >> 14;
        const float* faggB = g_fagg + (size_t)b*NPTS*D2;
        const float* G2B   = g_G2   + (size_t)b*NPTS*DD;

        int ids[16];
        load_ids(nidx + (size_t)p*KNN, ids);
        float g0[16], g1[16];
        #pragma unroll
        for (int k = 0; k < 16; k++) {
            const float* gp = &G2B[(size_t)ids[k]*DD];
            g0[k] = gp[lane];
            g1[k] = gp[lane + 32];
        }
        float fn[16];
        #pragma unroll
        for (int k = 0; k < 16; k++) fn[k] = faggB[(size_t)ids[k]*D2 + lane];

        const float* fxc = &g_fx1[(size_t)p*(D2*KNN) + lane*KNN];
        float4* xr0 = (float4*)&xw[lane*ST];
        xr0[0] = *(const float4*)&fxc[0];
        xr0[1] = *(const float4*)&fxc[4];
        xr0[2] = *(const float4*)&fxc[8];
        xr0[3] = *(const float4*)&fxc[12];
        __syncwarp();

        u64 accx[8];
        #pragma unroll
        for (int q = 0; q < 8; q++) accx[q] = 0ull;
        #pragma unroll 4
        for (int j = 0; j < D2; j++) {
            float wv = bb2T[j*D2 + lane];
            u64 wj = pck(wv, wv);
            const ulonglong2* xv = (const ulonglong2*)&xw[j*ST];
            #pragma unroll
            for (int q = 0; q < 4; q++) {
                ulonglong2 v = xv[q];
                accx[2*q]   = fma2(wj, v.x, accx[2*q]);
                accx[2*q+1] = fma2(wj, v.y, accx[2*q+1]);
            }
        }
        float fx2[16];
        #pragma unroll
        for (int q = 0; q < 8; q++) {
            float2 t = unpk(accx[q]);
            fx2[2*q]   = fmaxf(t.x*bs2 + bb2v, 0.f);
            fx2[2*q+1] = fmaxf(t.y*bs2 + bb2v, 0.f);
        }
        __syncwarp();

        #pragma unroll
        for (int q = 0; q < 4; q++)
            xr0[q] = make_float4(fx2[4*q], fx2[4*q+1], fx2[4*q+2], fx2[4*q+3]);
        __syncwarp();

        float att0[16], att1[16];
        att_half_P(fc2P, xw, lane, g0, g1, att0, att1);

        float agg0 = softagg(att0, fn);
        float agg1 = softagg(att1, fx2);
        __syncwarp();
        xw[lane] = agg0; xw[lane+32] = agg1;
        __syncwarp();

        u64 aA = 0ull, aB = 0ull;
        #pragma unroll
        for (int cc2 = 0; cc2 < 32; cc2++) {
            u64 xp = *(const u64*)&xw[2*cc2];
            aA = fma2(*(const u64*)&a2P[cc2*128 + lane*2], xp, aA);
            aB = fma2(*(const u64*)&a2P[cc2*128 + (lane+32)*2], xp, aB);
        }
        float2 tA = unpk(aA), tB = unpk(aB);
        float* lp = g_lfa + (size_t)p*DD;
        lp[lane]      = fmaxf((tA.x + tA.y)*a2sv[lane]      + a2bv[lane],      0.f);
        lp[lane + 32] = fmaxf((tB.x + tB.y)*a2sv[lane + 32] + a2bv[lane + 32], 0.f);
        __syncwarp();
    }
}

// ============================================================
// Kernel C2 v6: mlp2 + shortcut + leaky relu -> out [B,128,N]
// Thread = (pt, half, cgroup): 24 u64 activations/thread, partials
// combined via shfl_xor(1).  Pre-scaled combined weight table cmb[o][96].
// smem: cmb[12288] | bias[128] = 49.7 KB.  (256,3) -> 24 warps/SM.
// Block = 64 points; grid = P_TOT/64 = 1024.
// ============================================================
#define C2_PTS 64
#define SMEM_C2_FLOATS (12288 + 128)

__global__ void __launch_bounds__(256, 3) kC2(
    const float* __restrict__ m2W, const float* __restrict__ m2s, const float* __restrict__ m2b,
    const float* __restrict__ scW, const float* __restrict__ scs, const float* __restrict__ scb,
    float* __restrict__ out)
{
    extern __shared__ float sm[];
    float* cmb  = sm;          // [o*96 + cg*48 + c]  pre-scaled weights
    float* bias = sm + 12288;  // [o] = m2b[o] + scb[o]

    int tid = threadIdx.x;
    for (int i = tid; i < 12288; i += 256) {
        int o = i / 96, r = i - o*96;
        float v;
        if (r < 64) v = m2W[o*DD + r] * m2s[o];
        else        v = scW[o*D2 + (r - 64)] * scs[o];
        cmb[i] = v;
    }
    for (int i = tid; i < DOUT; i += 256) bias[i] = m2b[i] + scb[i];
    __syncthreads();

    int w    = tid >> 5, lane = tid & 31;
    int half = w & 1;
    int pt   = (w >> 1)*16 + (lane >> 1);
    int cg   = lane & 1;
    size_t p = (size_t)blockIdx.x * C2_PTS + pt;
    int b = (int)(p >> 14), n = (int)(p & (NPTS-1));

    // 24 u64 activations per thread
    u64 A[24];
    if (cg == 0) {
        const ulonglong2* lp = (const ulonglong2*)&g_lfa[p*DD];
        #pragma unroll
        for (int q = 0; q < 12; q++) { ulonglong2 v = lp[q]; A[2*q] = v.x; A[2*q+1] = v.y; }
    } else {
        const ulonglong2* lp = (const ulonglong2*)&g_lfa[p*DD + 48];
        #pragma unroll
        for (int q = 0; q < 4; q++) { ulonglong2 v = lp[q]; A[2*q] = v.x; A[2*q+1] = v.y; }
        const ulonglong2* fp = (const ulonglong2*)&g_featT[p*CIN];
        #pragma unroll
        for (int q = 0; q < 8; q++) { ulonglong2 v = fp[q]; A[8+2*q] = v.x; A[8+2*q+1] = v.y; }
    }

    const float* wbase = cmb + cg*48;
    float* outB = out + ((size_t)b*DOUT + half*64)*NPTS + n;
    #pragma unroll 2
    for (int oc = 0; oc < 64; oc++) {
        int o = half*64 + oc;
        const ulonglong2* wp = (const ulonglong2*)&wbase[o*96];
        u64 acc0 = 0ull, acc1 = 0ull;
        #pragma unroll
        for (int c = 0; c < 12; c++) {
            ulonglong2 wv = wp[c];
            acc0 = fma2(wv.x, A[2*c],   acc0);
            acc1 = fma2(wv.y, A[2*c+1], acc1);
        }
        float2 t0 = unpk(acc0), t1 = unpk(acc1);
        float partial = t0.x + t0.y + t1.x + t1.y;
        float total = partial + __shfl_xor_sync(0xffffffffu, partial, 1);
        if (cg == 0) {
            float v = total + bias[o];
            outB[(size_t)oc*NPTS] = v > 0.f ? v : 0.2f*v;
        }
    }
}

// ============================================================
extern "C" void kernel_launch(void* const* d_in, const int* in_sizes, int n_in,
                              void* d_out, int out_size)
{
    const float* feature = (const float*)d_in[0];
    const float* xyz     = (const float*)d_in[1];
    const int*   nidx    = (const int*)  d_in[2];
    const float* mlp1W = (const float*)d_in[3];
    const float* mlp1s = (const float*)d_in[4];
    const float* mlp1b = (const float*)d_in[5];
    const float* bb1W  = (const float*)d_in[6];
    const float* bb1s  = (const float*)d_in[7];
    const float* bb1b  = (const float*)d_in[8];
    const float* fc1   = (const float*)d_in[9];
    const float* a1W   = (const float*)d_in[10];
    const float* a1s   = (const float*)d_in[11];
    const float* a1b   = (const float*)d_in[12];
    const float* bb2W  = (const float*)d_in[13];
    const float* bb2s  = (const float*)d_in[14];
    const float* bb2b  = (const float*)d_in[15];
    const float* fc2   = (const float*)d_in[16];
    const float* a2W   = (const float*)d_in[17];
    const float* a2s   = (const float*)d_in[18];
    const float* a2b   = (const float*)d_in[19];
    const float* m2W   = (const float*)d_in[20];
    const float* m2s   = (const float*)d_in[21];
    const float* m2b   = (const float*)d_in[22];
    const float* scW   = (const float*)d_in[23];
    const float* scs   = (const float*)d_in[24];
    const float* scb   = (const float*)d_in[25];
    float* out = (float*)d_out;

    size_t smB  = SMEM_B_FLOATS  * sizeof(float);
    size_t smC1 = SMEM_C1_FLOATS * sizeof(float);
    size_t smC2 = SMEM_C2_FLOATS * sizeof(float);
    cudaFuncSetAttribute(kB,  cudaFuncAttributeMaxDynamicSharedMemorySize, (int)smB);
    cudaFuncSetAttribute(kC1, cudaFuncAttributeMaxDynamicSharedMemorySize, (int)smC1);
    cudaFuncSetAttribute(kC2, cudaFuncAttributeMaxDynamicSharedMemorySize, (int)smC2);

    kA<<<2048, dim3(32,8)>>>(feature, mlp1W, mlp1s, mlp1b, fc1);
    kB<<<296, 256, smB>>>(xyz, nidx, bb1W, bb1s, bb1b, fc1, a1W, a1s, a1b, fc2);
    kC1<<<296, 256, smC1>>>(nidx, bb2W, bb2s, bb2b, fc2, a2W, a2s, a2b);
    kC2<<<P_TOT/C2_PTS, 256, smC2>>>(m2W, m2s, m2b, scW, scs, scb, out);
}